// round 4
// baseline (speedup 1.0000x reference)
#include <cuda_runtime.h>
#include <cuda_bf16.h>
#include <stdint.h>

#define NB 16
#define NN 1024
#define DD 64
#define OUT_OFF ((size_t)NB * NN * NN)

// ---------------- scratch (device globals; no allocation) ----------------
__device__ float g_rowmean[NB*NN];
__device__ float g_diag[NB*NN];
__device__ float g_r[NB*NN];            // c3*rowmean + c4*diag + p1
__device__ float g_s[NB];               // c1*mean_all + c2*mean_diag + p2
__device__ float g_pg1[NB*DD];
__device__ float g_pg2[NB*DD];
__device__ float g_X2tT[(size_t)NB*DD*NN];   // X2_t transposed: [b][e][j]

// ---------------- packed fp32x2 helpers ----------------
__device__ __forceinline__ void fma2(unsigned long long &d,
                                     unsigned long long a,
                                     unsigned long long b) {
    asm("fma.rn.f32x2 %0, %1, %2, %0;" : "+l"(d) : "l"(a), "l"(b));
}
__device__ __forceinline__ float psum(unsigned long long v) {
    return __uint_as_float((unsigned)v) + __uint_as_float((unsigned)(v >> 32));
}

// ---------------- kernel 1: per-row stats (rowmean, diag, r) -------------
__global__ __launch_bounds__(256) void k_row_stats(
    const float* __restrict__ A, const float* __restrict__ X,
    const float* __restrict__ coeffs, const float* __restrict__ wA1)
{
    int gw = blockIdx.x * 8 + (threadIdx.x >> 5);   // global row 0..16383
    int lane = threadIdx.x & 31;
    const float4* arow = reinterpret_cast<const float4*>(A) + (size_t)gw * (NN/4);
    float s = 0.f;
#pragma unroll
    for (int w = 0; w < 8; ++w) {
        float4 v = arow[lane + (w << 5)];
        s += (v.x + v.y) + (v.z + v.w);
    }
    const float* xrow = X + (size_t)gw * DD;
    float p = xrow[lane] * wA1[lane] + xrow[lane+32] * wA1[lane+32];
#pragma unroll
    for (int o = 16; o; o >>= 1) {
        s += __shfl_xor_sync(0xffffffffu, s, o);
        p += __shfl_xor_sync(0xffffffffu, p, o);
    }
    if (lane == 0) {
        int i = gw & (NN-1);
        float d = A[(size_t)gw*NN + i];
        float rm = s * (1.f/NN);
        g_rowmean[gw] = rm;
        g_diag[gw]    = d;
        g_r[gw]       = coeffs[3]*rm + coeffs[4]*d + p;
    }
}

// ---------------- kernel 2: per-batch stats (s, pg1, pg2) ----------------
__global__ __launch_bounds__(256) void k_batch_stats(
    const float* __restrict__ X, const float* __restrict__ coeffs,
    const float* __restrict__ wA2,
    const float* __restrict__ w12, const float* __restrict__ w15, const float* __restrict__ w16,
    const float* __restrict__ w22, const float* __restrict__ w25, const float* __restrict__ w26)
{
    int b = blockIdx.x, t = threadIdx.x;
    __shared__ float red[256];
    __shared__ float sm_meanX[DD];
    __shared__ float sm_mall, sm_mdiag;

    float v1 = 0.f, v2 = 0.f;
    for (int i = t; i < NN; i += 256) { v1 += g_rowmean[b*NN+i]; v2 += g_diag[b*NN+i]; }
    red[t] = v1; __syncthreads();
    for (int o = 128; o > 0; o >>= 1) { if (t < o) red[t] += red[t+o]; __syncthreads(); }
    if (t == 0) sm_mall = red[0]*(1.f/NN);
    __syncthreads();
    red[t] = v2; __syncthreads();
    for (int o = 128; o > 0; o >>= 1) { if (t < o) red[t] += red[t+o]; __syncthreads(); }
    if (t == 0) sm_mdiag = red[0]*(1.f/NN);
    __syncthreads();

    int d = t & 63, g = t >> 6;
    float xs = 0.f;
    for (int j = g; j < NN; j += 4) xs += X[((size_t)b*NN + j)*DD + d];
    red[t] = xs; __syncthreads();
    if (g == 0) sm_meanX[d] = (red[d] + red[d+64] + red[d+128] + red[d+192]) * (1.f/NN);
    __syncthreads();

    float mall = sm_mall, mdiag = sm_mdiag;
    if (t == 0) {
        float p2 = 0.f;
        for (int k = 0; k < DD; ++k) p2 += sm_meanX[k]*wA2[k];
        g_s[b] = coeffs[1]*mall + coeffs[2]*mdiag + p2;
    } else if (t >= 64 && t < 128) {
        int e = t - 64;
        float a = 0.f;
        for (int k = 0; k < DD; ++k) a += sm_meanX[k]*w12[e*DD+k];
        g_pg1[b*DD+e] = a + mdiag*w15[e] + mall*w16[e];
    } else if (t >= 128 && t < 192) {
        int e = t - 128;
        float a = 0.f;
        for (int k = 0; k < DD; ++k) a += sm_meanX[k]*w22[e*DD+k];
        g_pg2[b*DD+e] = a + mdiag*w25[e] + mall*w26[e];
    }
}

// ---------------- kernel 3: node transforms X1_t, X2_t^T -----------------
// dynamic smem: Xs[128*64] | W1[64*68] | W2[64*68]  (67584 B)
__global__ __launch_bounds__(256) void k_node(
    const float* __restrict__ X,
    const float* __restrict__ w11, const float* __restrict__ w13, const float* __restrict__ w14,
    const float* __restrict__ w21, const float* __restrict__ w23, const float* __restrict__ w24,
    float* __restrict__ x1o)
{
    extern __shared__ __align__(16) float sm[];
    float* Xs = sm;               // [128][64]
    float* W1 = sm + 128*DD;      // [64][68]
    float* W2 = W1 + 64*68;       // [64][68]

    const int b = blockIdx.y;
    const int it0 = blockIdx.x << 7;    // 128 rows per block
    const int tid = threadIdx.x;
    const int c4 = tid & 15, r0 = tid >> 4;   // r0 0..15
    const int ci = c4 << 2;

    const float* Xb = X + ((size_t)b*NN + it0)*DD;
#pragma unroll
    for (int t = 0; t < 8; ++t) {
        int row = r0 + (t << 4);
        *reinterpret_cast<float4*>(Xs + row*DD + ci) =
            *reinterpret_cast<const float4*>(Xb + (size_t)row*DD + ci);
    }
#pragma unroll
    for (int t = 0; t < 4; ++t) {
        int e = r0 + (t << 4);
        *reinterpret_cast<float4*>(W1 + e*68 + ci) = *reinterpret_cast<const float4*>(w11 + e*DD + ci);
        *reinterpret_cast<float4*>(W2 + e*68 + ci) = *reinterpret_cast<const float4*>(w21 + e*DD + ci);
    }
    __syncthreads();

    const int tx = tid & 15, ty = tid >> 4;
    const int e0 = tx << 2, i0 = ty << 3;   // i0 0..120

    float rmv[8], dgv[8];
#pragma unroll
    for (int r = 0; r < 8; ++r) {
        int row = b*NN + it0 + i0 + r;
        rmv[r] = g_rowmean[row];
        dgv[r] = g_diag[row];
    }

    unsigned long long acc[8][4];

    // ---- pass 1: X1_t -> x1o ----
#pragma unroll
    for (int r = 0; r < 8; ++r)
#pragma unroll
        for (int q = 0; q < 4; ++q) acc[r][q] = 0ull;
#pragma unroll 2
    for (int d = 0; d < DD; d += 4) {
        ulonglong2 a[8];
#pragma unroll
        for (int r = 0; r < 8; ++r)
            a[r] = *reinterpret_cast<const ulonglong2*>(Xs + (i0+r)*DD + d);
#pragma unroll
        for (int q = 0; q < 4; ++q) {
            ulonglong2 bv = *reinterpret_cast<const ulonglong2*>(W1 + (e0+q)*68 + d);
#pragma unroll
            for (int r = 0; r < 8; ++r) { fma2(acc[r][q], a[r].x, bv.x); fma2(acc[r][q], a[r].y, bv.y); }
        }
    }
    {
        float4 wc = *reinterpret_cast<const float4*>(w13 + e0);
        float4 wd = *reinterpret_cast<const float4*>(w14 + e0);
        float4 pg = *reinterpret_cast<const float4*>(g_pg1 + b*DD + e0);
#pragma unroll
        for (int r = 0; r < 8; ++r) {
            float4 o;
            o.x = psum(acc[r][0]) + rmv[r]*wc.x + dgv[r]*wd.x + pg.x;
            o.y = psum(acc[r][1]) + rmv[r]*wc.y + dgv[r]*wd.y + pg.y;
            o.z = psum(acc[r][2]) + rmv[r]*wc.z + dgv[r]*wd.z + pg.z;
            o.w = psum(acc[r][3]) + rmv[r]*wc.w + dgv[r]*wd.w + pg.w;
            *reinterpret_cast<float4*>(x1o + ((size_t)b*NN + it0 + i0 + r)*DD + e0) = o;
        }
    }

    // ---- pass 2: X2_t -> registers, then SMEM-bounce transpose ----
#pragma unroll
    for (int r = 0; r < 8; ++r)
#pragma unroll
        for (int q = 0; q < 4; ++q) acc[r][q] = 0ull;
#pragma unroll 2
    for (int d = 0; d < DD; d += 4) {
        ulonglong2 a[8];
#pragma unroll
        for (int r = 0; r < 8; ++r)
            a[r] = *reinterpret_cast<const ulonglong2*>(Xs + (i0+r)*DD + d);
#pragma unroll
        for (int q = 0; q < 4; ++q) {
            ulonglong2 bv = *reinterpret_cast<const ulonglong2*>(W2 + (e0+q)*68 + d);
#pragma unroll
            for (int r = 0; r < 8; ++r) { fma2(acc[r][q], a[r].x, bv.x); fma2(acc[r][q], a[r].y, bv.y); }
        }
    }
    float4 o2v[8];
    {
        float4 wc = *reinterpret_cast<const float4*>(w23 + e0);
        float4 wd = *reinterpret_cast<const float4*>(w24 + e0);
        float4 pg = *reinterpret_cast<const float4*>(g_pg2 + b*DD + e0);
#pragma unroll
        for (int r = 0; r < 8; ++r) {
            o2v[r].x = psum(acc[r][0]) + rmv[r]*wc.x + dgv[r]*wd.x + pg.x;
            o2v[r].y = psum(acc[r][1]) + rmv[r]*wc.y + dgv[r]*wd.y + pg.y;
            o2v[r].z = psum(acc[r][2]) + rmv[r]*wc.z + dgv[r]*wd.z + pg.z;
            o2v[r].w = psum(acc[r][3]) + rmv[r]*wc.w + dgv[r]*wd.w + pg.w;
        }
    }
    __syncthreads();   // all reads of Xs done -> reuse as transpose buffer T[128][64]
#pragma unroll
    for (int r = 0; r < 8; ++r)
        *reinterpret_cast<float4*>(Xs + (i0+r)*DD + e0) = o2v[r];
    __syncthreads();

    // transposed write: g_X2tT[b][e][j]
    const int e = tid & 63, rc = tid >> 6;   // rc 0..3
#pragma unroll
    for (int rr = 0; rr < 8; ++rr) {
        int rowl = (rc << 5) + (rr << 2);
        float4 v;
        v.x = Xs[(rowl+0)*DD + e];
        v.y = Xs[(rowl+1)*DD + e];
        v.z = Xs[(rowl+2)*DD + e];
        v.w = Xs[(rowl+3)*DD + e];
        *reinterpret_cast<float4*>(g_X2tT + ((size_t)b*DD + e)*NN + it0 + rowl) = v;
    }
}

// ---------------- kernel 4: fused A_t construction + GEMM ----------------
// 64x64 tile, 256 threads. Lane = output row (A reads: 1 swizzled LDS.128,
// reused 32x); warp owns 16 e-columns (B reads: warp-uniform broadcast LDS,
// 1 crossbar cycle each). Crossbar cost/SM drops ~2.6x vs R3 -> FMA-bound.
__global__ __launch_bounds__(256, 2) void k_gemm(
    const float* __restrict__ A, const float* __restrict__ coeffs,
    float* __restrict__ At, float* __restrict__ x1o)
{
    __shared__ __align__(16) float4 Ast[64*16];   // phys = row*16 + (kc4 ^ (row&15))
    __shared__ __align__(16) float4 Bst[64*16];   // phys = e*16 + kc4 (broadcast reads)

    const int b = blockIdx.y, it0 = blockIdx.x << 6;
    const int tid = threadIdx.x;
    const int c4 = tid & 15, r0 = tid >> 4;     // loader coords
    const int ci = c4 << 2;
    const int wid = tid >> 5, lane = tid & 31;  // compute coords
    const int irow = ((wid & 1) << 5) + lane;   // output row within tile
    const int e0 = (wid >> 1) << 4;             // 16-wide e slice per warp

    const float c0 = coeffs[0];
    const float sb = g_s[b];
    float rloc[4];                               // s + r_i for owned load rows
#pragma unroll
    for (int t = 0; t < 4; ++t) rloc[t] = sb + g_r[b*NN + it0 + r0 + (t << 4)];

    const float* Ab = A  + ((size_t)b*NN + it0)*NN;
    float*       Ob = At + ((size_t)b*NN + it0)*NN;
    const float* Bb = g_X2tT + (size_t)b*DD*NN;

    unsigned long long acc[16];
#pragma unroll
    for (int q = 0; q < 16; ++q) acc[q] = 0ull;

    float4 Ar[4], Br[4], rjv;
    // prologue: prefetch k-tile 0
    rjv = *reinterpret_cast<const float4*>(g_r + b*NN + ci);
#pragma unroll
    for (int t = 0; t < 4; ++t) {
        int row = r0 + (t << 4);
        Ar[t] = *reinterpret_cast<const float4*>(Ab + (size_t)row*NN + ci);
        Br[t] = *reinterpret_cast<const float4*>(Bb + (size_t)row*NN + ci);
    }

    for (int kt = 0; kt < 16; ++kt) {
        const int k0 = kt << 6;
        __syncthreads();   // previous tile's compute done
#pragma unroll
        for (int t = 0; t < 4; ++t) {
            int row = r0 + (t << 4);
            float4 atv;
            atv.x = fmaf(c0, Ar[t].x, rloc[t] + rjv.x);
            atv.y = fmaf(c0, Ar[t].y, rloc[t] + rjv.y);
            atv.z = fmaf(c0, Ar[t].z, rloc[t] + rjv.z);
            atv.w = fmaf(c0, Ar[t].w, rloc[t] + rjv.w);
            *reinterpret_cast<float4*>(Ob + (size_t)row*NN + k0 + ci) = atv;   // A_t out
            Ast[(row << 4) + (c4 ^ (row & 15))] = atv;
            Bst[(row << 4) + c4] = Br[t];
        }
        __syncthreads();
        if (kt < 15) {   // prefetch next k-tile; LDG latency hidden by compute
            const int kn = (kt + 1) << 6;
            rjv = *reinterpret_cast<const float4*>(g_r + b*NN + kn + ci);
#pragma unroll
            for (int t = 0; t < 4; ++t) {
                int row = r0 + (t << 4);
                Ar[t] = *reinterpret_cast<const float4*>(Ab + (size_t)row*NN + kn + ci);
                Br[t] = *reinterpret_cast<const float4*>(Bb + (size_t)row*NN + kn + ci);
            }
        }
#pragma unroll
        for (int kc4 = 0; kc4 < 16; ++kc4) {
            ulonglong2 a = *reinterpret_cast<const ulonglong2*>(
                &Ast[(irow << 4) + (kc4 ^ (irow & 15))]);
#pragma unroll
            for (int q = 0; q < 16; ++q) {
                ulonglong2 bv = *reinterpret_cast<const ulonglong2*>(
                    &Bst[((e0 + q) << 4) + kc4]);
                fma2(acc[q], a.x, bv.x);
                fma2(acc[q], a.y, bv.y);
            }
        }
    }

    const float inv = 1.0f / 1024.0f;
    {
        size_t off = ((size_t)b*NN + it0 + irow)*DD + e0;
#pragma unroll
        for (int q4 = 0; q4 < 4; ++q4) {
            float4 x1 = *reinterpret_cast<const float4*>(x1o + off + (q4 << 2));
            float4 o;
            o.x = psum(acc[q4*4+0])*inv + x1.x;
            o.y = psum(acc[q4*4+1])*inv + x1.y;
            o.z = psum(acc[q4*4+2])*inv + x1.z;
            o.w = psum(acc[q4*4+3])*inv + x1.w;
            *reinterpret_cast<float4*>(x1o + off + (q4 << 2)) = o;
        }
    }
}

// ---------------- launch ----------------
extern "C" void kernel_launch(void* const* d_in, const int* in_sizes, int n_in,
                              void* d_out, int out_size)
{
    const float* A      = (const float*)d_in[0];
    const float* X      = (const float*)d_in[1];
    const float* coeffs = (const float*)d_in[2];
    const float* wA1    = (const float*)d_in[3];
    const float* wA2    = (const float*)d_in[4];
    const float* w11    = (const float*)d_in[5];
    const float* w12    = (const float*)d_in[6];
    const float* w13    = (const float*)d_in[7];
    const float* w14    = (const float*)d_in[8];
    const float* w15    = (const float*)d_in[9];
    const float* w16    = (const float*)d_in[10];
    const float* w21    = (const float*)d_in[11];
    const float* w22    = (const float*)d_in[12];
    const float* w23    = (const float*)d_in[13];
    const float* w24    = (const float*)d_in[14];
    const float* w25    = (const float*)d_in[15];
    const float* w26    = (const float*)d_in[16];

    float* out = (float*)d_out;
    float* x1o = out + OUT_OFF;

    const int NODE_SMEM = (128*DD + 2*64*68) * (int)sizeof(float);  // 67584
    cudaFuncSetAttribute(k_node, cudaFuncAttributeMaxDynamicSharedMemorySize, NODE_SMEM);

    k_row_stats  <<<2048, 256>>>(A, X, coeffs, wA1);
    k_batch_stats<<<16,   256>>>(X, coeffs, wA2, w12, w15, w16, w22, w25, w26);
    k_node       <<<dim3(8,16), 256, NODE_SMEM>>>(X, w11, w13, w14, w21, w23, w24, x1o);
    k_gemm       <<<dim3(16,16), 256>>>(A, coeffs, out, x1o);
}

// round 5
// speedup vs baseline: 1.2186x; 1.2186x over previous
#include <cuda_runtime.h>
#include <cuda_bf16.h>
#include <stdint.h>

#define NB 16
#define NN 1024
#define DD 64
#define OUT_OFF ((size_t)NB * NN * NN)

// ---------------- scratch (device globals; no allocation) ----------------
__device__ float g_rowmean[NB*NN];
__device__ float g_diag[NB*NN];
__device__ float g_r[NB*NN];            // c3*rowmean + c4*diag + p1
__device__ float g_s[NB];               // c1*mean_all + c2*mean_diag + p2
__device__ float g_pg1[NB*DD];
__device__ float g_pg2[NB*DD];
__device__ float g_X2tT[(size_t)NB*DD*NN];   // X2_t transposed: [b][e][j]

// ---------------- packed fp32x2 helpers ----------------
__device__ __forceinline__ void fma2(unsigned long long &d,
                                     unsigned long long a,
                                     unsigned long long b) {
    asm("fma.rn.f32x2 %0, %1, %2, %0;" : "+l"(d) : "l"(a), "l"(b));
}
__device__ __forceinline__ float psum(unsigned long long v) {
    return __uint_as_float((unsigned)v) + __uint_as_float((unsigned)(v >> 32));
}

// ---------------- kernel 1: per-row stats (rowmean, diag, r) -------------
__global__ __launch_bounds__(256) void k_row_stats(
    const float* __restrict__ A, const float* __restrict__ X,
    const float* __restrict__ coeffs, const float* __restrict__ wA1)
{
    int gw = blockIdx.x * 8 + (threadIdx.x >> 5);   // global row 0..16383
    int lane = threadIdx.x & 31;
    const float4* arow = reinterpret_cast<const float4*>(A) + (size_t)gw * (NN/4);
    float s = 0.f;
#pragma unroll
    for (int w = 0; w < 8; ++w) {
        float4 v = arow[lane + (w << 5)];
        s += (v.x + v.y) + (v.z + v.w);
    }
    const float* xrow = X + (size_t)gw * DD;
    float p = xrow[lane] * wA1[lane] + xrow[lane+32] * wA1[lane+32];
#pragma unroll
    for (int o = 16; o; o >>= 1) {
        s += __shfl_xor_sync(0xffffffffu, s, o);
        p += __shfl_xor_sync(0xffffffffu, p, o);
    }
    if (lane == 0) {
        int i = gw & (NN-1);
        float d = A[(size_t)gw*NN + i];
        float rm = s * (1.f/NN);
        g_rowmean[gw] = rm;
        g_diag[gw]    = d;
        g_r[gw]       = coeffs[3]*rm + coeffs[4]*d + p;
    }
}

// ---------------- kernel 2: per-batch stats (s, pg1, pg2) ----------------
__global__ __launch_bounds__(256) void k_batch_stats(
    const float* __restrict__ X, const float* __restrict__ coeffs,
    const float* __restrict__ wA2,
    const float* __restrict__ w12, const float* __restrict__ w15, const float* __restrict__ w16,
    const float* __restrict__ w22, const float* __restrict__ w25, const float* __restrict__ w26)
{
    int b = blockIdx.x, t = threadIdx.x;
    __shared__ float red[256];
    __shared__ float sm_meanX[DD];
    __shared__ float sm_mall, sm_mdiag;

    float v1 = 0.f, v2 = 0.f;
    for (int i = t; i < NN; i += 256) { v1 += g_rowmean[b*NN+i]; v2 += g_diag[b*NN+i]; }
    red[t] = v1; __syncthreads();
    for (int o = 128; o > 0; o >>= 1) { if (t < o) red[t] += red[t+o]; __syncthreads(); }
    if (t == 0) sm_mall = red[0]*(1.f/NN);
    __syncthreads();
    red[t] = v2; __syncthreads();
    for (int o = 128; o > 0; o >>= 1) { if (t < o) red[t] += red[t+o]; __syncthreads(); }
    if (t == 0) sm_mdiag = red[0]*(1.f/NN);
    __syncthreads();

    int d = t & 63, g = t >> 6;
    float xs = 0.f;
    for (int j = g; j < NN; j += 4) xs += X[((size_t)b*NN + j)*DD + d];
    red[t] = xs; __syncthreads();
    if (g == 0) sm_meanX[d] = (red[d] + red[d+64] + red[d+128] + red[d+192]) * (1.f/NN);
    __syncthreads();

    float mall = sm_mall, mdiag = sm_mdiag;
    if (t == 0) {
        float p2 = 0.f;
        for (int k = 0; k < DD; ++k) p2 += sm_meanX[k]*wA2[k];
        g_s[b] = coeffs[1]*mall + coeffs[2]*mdiag + p2;
    } else if (t >= 64 && t < 128) {
        int e = t - 64;
        float a = 0.f;
        for (int k = 0; k < DD; ++k) a += sm_meanX[k]*w12[e*DD+k];
        g_pg1[b*DD+e] = a + mdiag*w15[e] + mall*w16[e];
    } else if (t >= 128 && t < 192) {
        int e = t - 128;
        float a = 0.f;
        for (int k = 0; k < DD; ++k) a += sm_meanX[k]*w22[e*DD+k];
        g_pg2[b*DD+e] = a + mdiag*w25[e] + mall*w26[e];
    }
}

// ---------------- kernel 3: node transforms X1_t, X2_t^T -----------------
// dynamic smem: Xs[128*64] | W1[64*68] | W2[64*68]  (67584 B)
__global__ __launch_bounds__(256) void k_node(
    const float* __restrict__ X,
    const float* __restrict__ w11, const float* __restrict__ w13, const float* __restrict__ w14,
    const float* __restrict__ w21, const float* __restrict__ w23, const float* __restrict__ w24,
    float* __restrict__ x1o)
{
    extern __shared__ __align__(16) float sm[];
    float* Xs = sm;               // [128][64]
    float* W1 = sm + 128*DD;      // [64][68]
    float* W2 = W1 + 64*68;       // [64][68]

    const int b = blockIdx.y;
    const int it0 = blockIdx.x << 7;    // 128 rows per block
    const int tid = threadIdx.x;
    const int c4 = tid & 15, r0 = tid >> 4;   // r0 0..15
    const int ci = c4 << 2;

    const float* Xb = X + ((size_t)b*NN + it0)*DD;
#pragma unroll
    for (int t = 0; t < 8; ++t) {
        int row = r0 + (t << 4);
        *reinterpret_cast<float4*>(Xs + row*DD + ci) =
            *reinterpret_cast<const float4*>(Xb + (size_t)row*DD + ci);
    }
#pragma unroll
    for (int t = 0; t < 4; ++t) {
        int e = r0 + (t << 4);
        *reinterpret_cast<float4*>(W1 + e*68 + ci) = *reinterpret_cast<const float4*>(w11 + e*DD + ci);
        *reinterpret_cast<float4*>(W2 + e*68 + ci) = *reinterpret_cast<const float4*>(w21 + e*DD + ci);
    }
    __syncthreads();

    const int tx = tid & 15, ty = tid >> 4;
    const int e0 = tx << 2, i0 = ty << 3;   // i0 0..120

    float rmv[8], dgv[8];
#pragma unroll
    for (int r = 0; r < 8; ++r) {
        int row = b*NN + it0 + i0 + r;
        rmv[r] = g_rowmean[row];
        dgv[r] = g_diag[row];
    }

    unsigned long long acc[8][4];

    // ---- pass 1: X1_t -> x1o ----
#pragma unroll
    for (int r = 0; r < 8; ++r)
#pragma unroll
        for (int q = 0; q < 4; ++q) acc[r][q] = 0ull;
#pragma unroll 2
    for (int d = 0; d < DD; d += 4) {
        ulonglong2 a[8];
#pragma unroll
        for (int r = 0; r < 8; ++r)
            a[r] = *reinterpret_cast<const ulonglong2*>(Xs + (i0+r)*DD + d);
#pragma unroll
        for (int q = 0; q < 4; ++q) {
            ulonglong2 bv = *reinterpret_cast<const ulonglong2*>(W1 + (e0+q)*68 + d);
#pragma unroll
            for (int r = 0; r < 8; ++r) { fma2(acc[r][q], a[r].x, bv.x); fma2(acc[r][q], a[r].y, bv.y); }
        }
    }
    {
        float4 wc = *reinterpret_cast<const float4*>(w13 + e0);
        float4 wd = *reinterpret_cast<const float4*>(w14 + e0);
        float4 pg = *reinterpret_cast<const float4*>(g_pg1 + b*DD + e0);
#pragma unroll
        for (int r = 0; r < 8; ++r) {
            float4 o;
            o.x = psum(acc[r][0]) + rmv[r]*wc.x + dgv[r]*wd.x + pg.x;
            o.y = psum(acc[r][1]) + rmv[r]*wc.y + dgv[r]*wd.y + pg.y;
            o.z = psum(acc[r][2]) + rmv[r]*wc.z + dgv[r]*wd.z + pg.z;
            o.w = psum(acc[r][3]) + rmv[r]*wc.w + dgv[r]*wd.w + pg.w;
            *reinterpret_cast<float4*>(x1o + ((size_t)b*NN + it0 + i0 + r)*DD + e0) = o;
        }
    }

    // ---- pass 2: X2_t -> registers, then SMEM-bounce transpose ----
#pragma unroll
    for (int r = 0; r < 8; ++r)
#pragma unroll
        for (int q = 0; q < 4; ++q) acc[r][q] = 0ull;
#pragma unroll 2
    for (int d = 0; d < DD; d += 4) {
        ulonglong2 a[8];
#pragma unroll
        for (int r = 0; r < 8; ++r)
            a[r] = *reinterpret_cast<const ulonglong2*>(Xs + (i0+r)*DD + d);
#pragma unroll
        for (int q = 0; q < 4; ++q) {
            ulonglong2 bv = *reinterpret_cast<const ulonglong2*>(W2 + (e0+q)*68 + d);
#pragma unroll
            for (int r = 0; r < 8; ++r) { fma2(acc[r][q], a[r].x, bv.x); fma2(acc[r][q], a[r].y, bv.y); }
        }
    }
    float4 o2v[8];
    {
        float4 wc = *reinterpret_cast<const float4*>(w23 + e0);
        float4 wd = *reinterpret_cast<const float4*>(w24 + e0);
        float4 pg = *reinterpret_cast<const float4*>(g_pg2 + b*DD + e0);
#pragma unroll
        for (int r = 0; r < 8; ++r) {
            o2v[r].x = psum(acc[r][0]) + rmv[r]*wc.x + dgv[r]*wd.x + pg.x;
            o2v[r].y = psum(acc[r][1]) + rmv[r]*wc.y + dgv[r]*wd.y + pg.y;
            o2v[r].z = psum(acc[r][2]) + rmv[r]*wc.z + dgv[r]*wd.z + pg.z;
            o2v[r].w = psum(acc[r][3]) + rmv[r]*wc.w + dgv[r]*wd.w + pg.w;
        }
    }
    __syncthreads();   // all reads of Xs done -> reuse as transpose buffer T[128][64]
#pragma unroll
    for (int r = 0; r < 8; ++r)
        *reinterpret_cast<float4*>(Xs + (i0+r)*DD + e0) = o2v[r];
    __syncthreads();

    // transposed write: g_X2tT[b][e][j]
    const int e = tid & 63, rc = tid >> 6;   // rc 0..3
#pragma unroll
    for (int rr = 0; rr < 8; ++rr) {
        int rowl = (rc << 5) + (rr << 2);
        float4 v;
        v.x = Xs[(rowl+0)*DD + e];
        v.y = Xs[(rowl+1)*DD + e];
        v.z = Xs[(rowl+2)*DD + e];
        v.w = Xs[(rowl+3)*DD + e];
        *reinterpret_cast<float4*>(g_X2tT + ((size_t)b*DD + e)*NN + it0 + rowl) = v;
    }
}

// ---------------- kernel 4: fused A_t construction + GEMM ----------------
// 64x64 tile, 256 threads, 4x4 micro-tile (R3 mapping), fp32x2 K-pairs.
// 2-stage SMEM double buffer: ONE __syncthreads per k-tile; fill of the
// next stage + A_t STG overlap the current compute; LDG prefetch distance 2.
__global__ __launch_bounds__(256, 2) void k_gemm(
    const float* __restrict__ A, const float* __restrict__ coeffs,
    float* __restrict__ At, float* __restrict__ x1o)
{
    extern __shared__ __align__(16) float4 sm4[];
    float4* Ast = sm4;            // [stage][row*16 + kc4]
    float4* Bst = sm4 + 2048;     // [stage][e*16 + (kc4 ^ (e>>2))]

    const int b = blockIdx.y, it0 = blockIdx.x << 6;
    const int tid = threadIdx.x;
    const int c4 = tid & 15, r0 = tid >> 4;     // loader coords
    const int ci = c4 << 2;
    const int tx = tid & 15, ty = tid >> 4;     // compute coords
    const int e0 = tx << 2, i0 = ty << 2;       // 4x4 micro-tile

    const float c0 = coeffs[0];
    const float sb = g_s[b];
    float rloc[4];                               // s + r_i for owned load rows
#pragma unroll
    for (int t = 0; t < 4; ++t) rloc[t] = sb + g_r[b*NN + it0 + r0 + (t << 4)];

    const float* Ab = A  + ((size_t)b*NN + it0)*NN;
    float*       Ob = At + ((size_t)b*NN + it0)*NN;
    const float* Bb = g_X2tT + (size_t)b*DD*NN;

    unsigned long long acc[4][4];
#pragma unroll
    for (int r = 0; r < 4; ++r)
#pragma unroll
        for (int q = 0; q < 4; ++q) acc[r][q] = 0ull;

    float4 Ar[4], Br[4], rjv;

    // fetch tile tk into registers
    auto fetch = [&](int tk) {
        const int k0 = tk << 6;
        rjv = *reinterpret_cast<const float4*>(g_r + b*NN + k0 + ci);
#pragma unroll
        for (int t = 0; t < 4; ++t) {
            int row = r0 + (t << 4);
            Ar[t] = *reinterpret_cast<const float4*>(Ab + (size_t)row*NN + k0 + ci);
            Br[t] = *reinterpret_cast<const float4*>(Bb + (size_t)row*NN + k0 + ci);
        }
    };
    // transform + store tile tk (in regs) to smem stage stg; STG A_t
    auto fill = [&](int tk, int stg) {
        const int k0 = tk << 6;
        const int so = stg << 10;
#pragma unroll
        for (int t = 0; t < 4; ++t) {
            int row = r0 + (t << 4);
            float4 atv;
            atv.x = fmaf(c0, Ar[t].x, rloc[t] + rjv.x);
            atv.y = fmaf(c0, Ar[t].y, rloc[t] + rjv.y);
            atv.z = fmaf(c0, Ar[t].z, rloc[t] + rjv.z);
            atv.w = fmaf(c0, Ar[t].w, rloc[t] + rjv.w);
            *reinterpret_cast<float4*>(Ob + (size_t)row*NN + k0 + ci) = atv;   // A_t out
            Ast[so + (row << 4) + c4] = atv;
            Bst[so + (row << 4) + (c4 ^ (row >> 2))] = Br[t];
        }
    };

    // prologue: tile 0 -> stage 0; prefetch tile 1
    fetch(0);
    fill(0, 0);
    fetch(1);
    __syncthreads();

    for (int kt = 0; kt < 16; ++kt) {
        const int so = (kt & 1) << 10;
        if (kt < 15) fill(kt + 1, (kt + 1) & 1);   // regs hold tile kt+1
        if (kt < 14) fetch(kt + 2);                // LDG overlaps compute below
#pragma unroll
        for (int kc4 = 0; kc4 < 16; ++kc4) {
            ulonglong2 a[4], bv[4];
#pragma unroll
            for (int r = 0; r < 4; ++r)
                a[r] = *reinterpret_cast<const ulonglong2*>(&Ast[so + ((i0+r) << 4) + kc4]);
#pragma unroll
            for (int q = 0; q < 4; ++q)
                bv[q] = *reinterpret_cast<const ulonglong2*>(&Bst[so + ((e0+q) << 4) + (kc4 ^ tx)]);
#pragma unroll
            for (int q = 0; q < 4; ++q)
#pragma unroll
                for (int r = 0; r < 4; ++r) {
                    fma2(acc[r][q], a[r].x, bv[q].x);
                    fma2(acc[r][q], a[r].y, bv[q].y);
                }
        }
        if (kt < 15) __syncthreads();
    }

    const float inv = 1.0f / 1024.0f;
#pragma unroll
    for (int r = 0; r < 4; ++r) {
        size_t off = ((size_t)b*NN + it0 + i0 + r)*DD + e0;
        float4 x1 = *reinterpret_cast<const float4*>(x1o + off);
        float4 o;
        o.x = psum(acc[r][0])*inv + x1.x;
        o.y = psum(acc[r][1])*inv + x1.y;
        o.z = psum(acc[r][2])*inv + x1.z;
        o.w = psum(acc[r][3])*inv + x1.w;
        *reinterpret_cast<float4*>(x1o + off) = o;
    }
}

// ---------------- launch ----------------
extern "C" void kernel_launch(void* const* d_in, const int* in_sizes, int n_in,
                              void* d_out, int out_size)
{
    const float* A      = (const float*)d_in[0];
    const float* X      = (const float*)d_in[1];
    const float* coeffs = (const float*)d_in[2];
    const float* wA1    = (const float*)d_in[3];
    const float* wA2    = (const float*)d_in[4];
    const float* w11    = (const float*)d_in[5];
    const float* w12    = (const float*)d_in[6];
    const float* w13    = (const float*)d_in[7];
    const float* w14    = (const float*)d_in[8];
    const float* w15    = (const float*)d_in[9];
    const float* w16    = (const float*)d_in[10];
    const float* w21    = (const float*)d_in[11];
    const float* w22    = (const float*)d_in[12];
    const float* w23    = (const float*)d_in[13];
    const float* w24    = (const float*)d_in[14];
    const float* w25    = (const float*)d_in[15];
    const float* w26    = (const float*)d_in[16];

    float* out = (float*)d_out;
    float* x1o = out + OUT_OFF;

    const int NODE_SMEM = (128*DD + 2*64*68) * (int)sizeof(float);  // 67584
    cudaFuncSetAttribute(k_node, cudaFuncAttributeMaxDynamicSharedMemorySize, NODE_SMEM);
    const int GEMM_SMEM = 4096 * (int)sizeof(float4);               // 65536
    cudaFuncSetAttribute(k_gemm, cudaFuncAttributeMaxDynamicSharedMemorySize, GEMM_SMEM);

    k_row_stats  <<<2048, 256>>>(A, X, coeffs, wA1);
    k_batch_stats<<<16,   256>>>(X, coeffs, wA2, w12, w15, w16, w22, w25, w26);
    k_node       <<<dim3(8,16), 256, NODE_SMEM>>>(X, w11, w13, w14, w21, w23, w24, x1o);
    k_gemm       <<<dim3(16,16), 256, GEMM_SMEM>>>(A, coeffs, out, x1o);
}

// round 7
// speedup vs baseline: 1.3304x; 1.0918x over previous
#include <cuda_runtime.h>
#include <cuda_bf16.h>
#include <stdint.h>

#define NB 16
#define NN 1024
#define DD 64
#define OUT_OFF ((size_t)NB * NN * NN)

// ---------------- scratch (device globals; no allocation) ----------------
__device__ float g_rowmean[NB*NN];
__device__ float g_diag[NB*NN];
__device__ float g_r[NB*NN];            // c3*rowmean + c4*diag + p1
__device__ float g_s[NB];               // c1*mean_all + c2*mean_diag + p2
__device__ float g_pg1[NB*DD];
__device__ float g_pg2[NB*DD];
__device__ float g_X2tT[(size_t)NB*DD*NN];   // X2_t transposed: [b][e][j]

// ---------------- packed fp32x2 helpers (k_node) ----------------
__device__ __forceinline__ void fma2(unsigned long long &d,
                                     unsigned long long a,
                                     unsigned long long b) {
    asm("fma.rn.f32x2 %0, %1, %2, %0;" : "+l"(d) : "l"(a), "l"(b));
}
__device__ __forceinline__ float psum(unsigned long long v) {
    return __uint_as_float((unsigned)v) + __uint_as_float((unsigned)(v >> 32));
}

// ---------------- tf32 split (register-side) ----------------
__device__ __forceinline__ void tf32pair(float v, uint32_t &h, uint32_t &l) {
    asm("cvt.rna.tf32.f32 %0, %1;" : "=r"(h) : "f"(v));
    float rmd = v - __uint_as_float(h);
    asm("cvt.rna.tf32.f32 %0, %1;" : "=r"(l) : "f"(rmd));
}

// ---------------- m16n8k8 tf32 mma (HMMA, baseline PTX) ----------------
__device__ __forceinline__ void mma8(float* c, const uint32_t* a,
                                     uint32_t b0, uint32_t b1) {
    asm volatile(
        "mma.sync.aligned.m16n8k8.row.col.f32.tf32.tf32.f32 "
        "{%0,%1,%2,%3}, {%4,%5,%6,%7}, {%8,%9}, {%0,%1,%2,%3};"
        : "+f"(c[0]), "+f"(c[1]), "+f"(c[2]), "+f"(c[3])
        : "r"(a[0]), "r"(a[1]), "r"(a[2]), "r"(a[3]), "r"(b0), "r"(b1));
}

// ---------------- kernel 1: per-row stats (rowmean, diag, r) -------------
__global__ __launch_bounds__(256) void k_row_stats(
    const float* __restrict__ A, const float* __restrict__ X,
    const float* __restrict__ coeffs, const float* __restrict__ wA1)
{
    int gw = blockIdx.x * 8 + (threadIdx.x >> 5);   // global row 0..16383
    int lane = threadIdx.x & 31;
    const float4* arow = reinterpret_cast<const float4*>(A) + (size_t)gw * (NN/4);
    float s = 0.f;
#pragma unroll
    for (int w = 0; w < 8; ++w) {
        float4 v = arow[lane + (w << 5)];
        s += (v.x + v.y) + (v.z + v.w);
    }
    const float* xrow = X + (size_t)gw * DD;
    float p = xrow[lane] * wA1[lane] + xrow[lane+32] * wA1[lane+32];
#pragma unroll
    for (int o = 16; o; o >>= 1) {
        s += __shfl_xor_sync(0xffffffffu, s, o);
        p += __shfl_xor_sync(0xffffffffu, p, o);
    }
    if (lane == 0) {
        int i = gw & (NN-1);
        float d = A[(size_t)gw*NN + i];
        float rm = s * (1.f/NN);
        g_rowmean[gw] = rm;
        g_diag[gw]    = d;
        g_r[gw]       = coeffs[3]*rm + coeffs[4]*d + p;
    }
}

// ---------------- kernel 2: per-batch stats (s, pg1, pg2) ----------------
__global__ __launch_bounds__(256) void k_batch_stats(
    const float* __restrict__ X, const float* __restrict__ coeffs,
    const float* __restrict__ wA2,
    const float* __restrict__ w12, const float* __restrict__ w15, const float* __restrict__ w16,
    const float* __restrict__ w22, const float* __restrict__ w25, const float* __restrict__ w26)
{
    int b = blockIdx.x, t = threadIdx.x;
    __shared__ float red[256];
    __shared__ float sm_meanX[DD];
    __shared__ float sm_mall, sm_mdiag;

    float v1 = 0.f, v2 = 0.f;
    for (int i = t; i < NN; i += 256) { v1 += g_rowmean[b*NN+i]; v2 += g_diag[b*NN+i]; }
    red[t] = v1; __syncthreads();
    for (int o = 128; o > 0; o >>= 1) { if (t < o) red[t] += red[t+o]; __syncthreads(); }
    if (t == 0) sm_mall = red[0]*(1.f/NN);
    __syncthreads();
    red[t] = v2; __syncthreads();
    for (int o = 128; o > 0; o >>= 1) { if (t < o) red[t] += red[t+o]; __syncthreads(); }
    if (t == 0) sm_mdiag = red[0]*(1.f/NN);
    __syncthreads();

    int d = t & 63, g = t >> 6;
    float xs = 0.f;
    for (int j = g; j < NN; j += 4) xs += X[((size_t)b*NN + j)*DD + d];
    red[t] = xs; __syncthreads();
    if (g == 0) sm_meanX[d] = (red[d] + red[d+64] + red[d+128] + red[d+192]) * (1.f/NN);
    __syncthreads();

    float mall = sm_mall, mdiag = sm_mdiag;
    if (t == 0) {
        float p2 = 0.f;
        for (int k = 0; k < DD; ++k) p2 += sm_meanX[k]*wA2[k];
        g_s[b] = coeffs[1]*mall + coeffs[2]*mdiag + p2;
    } else if (t >= 64 && t < 128) {
        int e = t - 64;
        float a = 0.f;
        for (int k = 0; k < DD; ++k) a += sm_meanX[k]*w12[e*DD+k];
        g_pg1[b*DD+e] = a + mdiag*w15[e] + mall*w16[e];
    } else if (t >= 128 && t < 192) {
        int e = t - 128;
        float a = 0.f;
        for (int k = 0; k < DD; ++k) a += sm_meanX[k]*w22[e*DD+k];
        g_pg2[b*DD+e] = a + mdiag*w25[e] + mall*w26[e];
    }
}

// ---------------- kernel 3: node transforms X1_t, X2_t^T -----------------
// dynamic smem: Xs[128*64] | W1[64*68] | W2[64*68]  (67584 B)
__global__ __launch_bounds__(256) void k_node(
    const float* __restrict__ X,
    const float* __restrict__ w11, const float* __restrict__ w13, const float* __restrict__ w14,
    const float* __restrict__ w21, const float* __restrict__ w23, const float* __restrict__ w24,
    float* __restrict__ x1o)
{
    extern __shared__ __align__(16) float sm[];
    float* Xs = sm;               // [128][64]
    float* W1 = sm + 128*DD;      // [64][68]
    float* W2 = W1 + 64*68;       // [64][68]

    const int b = blockIdx.y;
    const int it0 = blockIdx.x << 7;    // 128 rows per block
    const int tid = threadIdx.x;
    const int c4 = tid & 15, r0 = tid >> 4;   // r0 0..15
    const int ci = c4 << 2;

    const float* Xb = X + ((size_t)b*NN + it0)*DD;
#pragma unroll
    for (int t = 0; t < 8; ++t) {
        int row = r0 + (t << 4);
        *reinterpret_cast<float4*>(Xs + row*DD + ci) =
            *reinterpret_cast<const float4*>(Xb + (size_t)row*DD + ci);
    }
#pragma unroll
    for (int t = 0; t < 4; ++t) {
        int e = r0 + (t << 4);
        *reinterpret_cast<float4*>(W1 + e*68 + ci) = *reinterpret_cast<const float4*>(w11 + e*DD + ci);
        *reinterpret_cast<float4*>(W2 + e*68 + ci) = *reinterpret_cast<const float4*>(w21 + e*DD + ci);
    }
    __syncthreads();

    const int tx = tid & 15, ty = tid >> 4;
    const int e0 = tx << 2, i0 = ty << 3;   // i0 0..120

    float rmv[8], dgv[8];
#pragma unroll
    for (int r = 0; r < 8; ++r) {
        int row = b*NN + it0 + i0 + r;
        rmv[r] = g_rowmean[row];
        dgv[r] = g_diag[row];
    }

    unsigned long long acc[8][4];

    // ---- pass 1: X1_t -> x1o ----
#pragma unroll
    for (int r = 0; r < 8; ++r)
#pragma unroll
        for (int q = 0; q < 4; ++q) acc[r][q] = 0ull;
#pragma unroll 2
    for (int d = 0; d < DD; d += 4) {
        ulonglong2 a[8];
#pragma unroll
        for (int r = 0; r < 8; ++r)
            a[r] = *reinterpret_cast<const ulonglong2*>(Xs + (i0+r)*DD + d);
#pragma unroll
        for (int q = 0; q < 4; ++q) {
            ulonglong2 bv = *reinterpret_cast<const ulonglong2*>(W1 + (e0+q)*68 + d);
#pragma unroll
            for (int r = 0; r < 8; ++r) { fma2(acc[r][q], a[r].x, bv.x); fma2(acc[r][q], a[r].y, bv.y); }
        }
    }
    {
        float4 wc = *reinterpret_cast<const float4*>(w13 + e0);
        float4 wd = *reinterpret_cast<const float4*>(w14 + e0);
        float4 pg = *reinterpret_cast<const float4*>(g_pg1 + b*DD + e0);
#pragma unroll
        for (int r = 0; r < 8; ++r) {
            float4 o;
            o.x = psum(acc[r][0]) + rmv[r]*wc.x + dgv[r]*wd.x + pg.x;
            o.y = psum(acc[r][1]) + rmv[r]*wc.y + dgv[r]*wd.y + pg.y;
            o.z = psum(acc[r][2]) + rmv[r]*wc.z + dgv[r]*wd.z + pg.z;
            o.w = psum(acc[r][3]) + rmv[r]*wc.w + dgv[r]*wd.w + pg.w;
            *reinterpret_cast<float4*>(x1o + ((size_t)b*NN + it0 + i0 + r)*DD + e0) = o;
        }
    }

    // ---- pass 2: X2_t -> registers, then SMEM-bounce transpose ----
#pragma unroll
    for (int r = 0; r < 8; ++r)
#pragma unroll
        for (int q = 0; q < 4; ++q) acc[r][q] = 0ull;
#pragma unroll 2
    for (int d = 0; d < DD; d += 4) {
        ulonglong2 a[8];
#pragma unroll
        for (int r = 0; r < 8; ++r)
            a[r] = *reinterpret_cast<const ulonglong2*>(Xs + (i0+r)*DD + d);
#pragma unroll
        for (int q = 0; q < 4; ++q) {
            ulonglong2 bv = *reinterpret_cast<const ulonglong2*>(W2 + (e0+q)*68 + d);
#pragma unroll
            for (int r = 0; r < 8; ++r) { fma2(acc[r][q], a[r].x, bv.x); fma2(acc[r][q], a[r].y, bv.y); }
        }
    }
    float4 o2v[8];
    {
        float4 wc = *reinterpret_cast<const float4*>(w23 + e0);
        float4 wd = *reinterpret_cast<const float4*>(w24 + e0);
        float4 pg = *reinterpret_cast<const float4*>(g_pg2 + b*DD + e0);
#pragma unroll
        for (int r = 0; r < 8; ++r) {
            o2v[r].x = psum(acc[r][0]) + rmv[r]*wc.x + dgv[r]*wd.x + pg.x;
            o2v[r].y = psum(acc[r][1]) + rmv[r]*wc.y + dgv[r]*wd.y + pg.y;
            o2v[r].z = psum(acc[r][2]) + rmv[r]*wc.z + dgv[r]*wd.z + pg.z;
            o2v[r].w = psum(acc[r][3]) + rmv[r]*wc.w + dgv[r]*wd.w + pg.w;
        }
    }
    __syncthreads();   // all reads of Xs done -> reuse as transpose buffer
#pragma unroll
    for (int r = 0; r < 8; ++r)
        *reinterpret_cast<float4*>(Xs + (i0+r)*DD + e0) = o2v[r];
    __syncthreads();

    // transposed write: g_X2tT[b][e][j]
    const int e = tid & 63, rc = tid >> 6;   // rc 0..3
#pragma unroll
    for (int rr = 0; rr < 8; ++rr) {
        int rowl = (rc << 5) + (rr << 2);
        float4 v;
        v.x = Xs[(rowl+0)*DD + e];
        v.y = Xs[(rowl+1)*DD + e];
        v.z = Xs[(rowl+2)*DD + e];
        v.w = Xs[(rowl+3)*DD + e];
        *reinterpret_cast<float4*>(g_X2tT + ((size_t)b*DD + e)*NN + it0 + rowl) = v;
    }
}

// ---------------- kernel 4: HMMA tf32 GEMM (3xTF32, mma.sync) ------------
// 256 threads, 128x64 M/E tile per block, KC=64, double-buffered fp32 smem.
// Each warp: 16 rows x 64 e. Fragments split hi/lo in registers; three
// mma passes (hh, hl, lh) per kstep. One __syncthreads per stage.
#define STG_F 13056   // floats per stage: A 128*68 + B 64*68
__global__ __launch_bounds__(256, 1) void k_gemm(
    const float* __restrict__ A, const float* __restrict__ coeffs,
    float* __restrict__ At, float* __restrict__ x1o)
{
    extern __shared__ __align__(16) float sm[];
    const int tid = threadIdx.x;
    const int wid = tid >> 5, lane = tid & 31;
    const int b = blockIdx.y, it0 = blockIdx.x << 7;

    // loader coords
    const int rb = tid >> 4;            // 0..15 (A rows rb+16i)
    const int ci = (tid & 15) << 2;     // 0..60
    const int eb = tid >> 2;            // 0..63 (B row)
    const int kq = (tid & 3) << 4;      // 0,16,32,48

    const float c0 = coeffs[0];
    const float sbv = g_s[b];
    float rloc[8];
#pragma unroll
    for (int i = 0; i < 8; ++i) rloc[i] = sbv + g_r[b*NN + it0 + rb + (i << 4)];

    const float* Ab = A  + ((size_t)b*NN + it0)*NN;
    float*       Ob = At + ((size_t)b*NN + it0)*NN;
    const float* Bb = g_X2tT + (size_t)b*DD*NN;

    float acc[8][4];
#pragma unroll
    for (int nt = 0; nt < 8; ++nt)
#pragma unroll
        for (int q = 0; q < 4; ++q) acc[nt][q] = 0.f;

    float4 Ar[8], Brr[4], rjv;
    auto fetch = [&](int s) {
        const int k0 = s << 6;
        rjv = *reinterpret_cast<const float4*>(g_r + b*NN + k0 + ci);
#pragma unroll
        for (int i = 0; i < 8; ++i)
            Ar[i] = *reinterpret_cast<const float4*>(Ab + (size_t)(rb + (i << 4))*NN + k0 + ci);
#pragma unroll
        for (int q = 0; q < 4; ++q)
            Brr[q] = *reinterpret_cast<const float4*>(Bb + (size_t)eb*NN + k0 + kq + (q << 2));
    };
    auto fill = [&](int s, int buf) {
        const int k0 = s << 6;
        float* As = sm + buf * STG_F;
        float* Bs = As + 128*68;
#pragma unroll
        for (int i = 0; i < 8; ++i) {
            int row = rb + (i << 4);
            float4 atv;
            atv.x = fmaf(c0, Ar[i].x, rloc[i] + rjv.x);
            atv.y = fmaf(c0, Ar[i].y, rloc[i] + rjv.y);
            atv.z = fmaf(c0, Ar[i].z, rloc[i] + rjv.z);
            atv.w = fmaf(c0, Ar[i].w, rloc[i] + rjv.w);
            *reinterpret_cast<float4*>(Ob + (size_t)row*NN + k0 + ci) = atv;   // A_t out
            *reinterpret_cast<float4*>(As + row*68 + ci) = atv;
        }
#pragma unroll
        for (int q = 0; q < 4; ++q)
            *reinterpret_cast<float4*>(Bs + eb*68 + kq + (q << 2)) = Brr[q];
    };

    const int g = lane >> 2, t = lane & 3, m0 = wid << 4;

    fetch(0);
    fill(0, 0);
    __syncthreads();

    for (int s = 0; s < 16; ++s) {
        if (s < 15) fetch(s + 1);        // LDG in flight behind MMAs
        const float* As = sm + (s & 1) * STG_F;
        const float* Bs = As + 128*68;
#pragma unroll
        for (int ks = 0; ks < 8; ++ks) {
            const int kk = ks << 3;
            uint32_t ah[4], al[4];
            tf32pair(As[(m0+g  )*68 + kk + t    ], ah[0], al[0]);
            tf32pair(As[(m0+g+8)*68 + kk + t    ], ah[1], al[1]);
            tf32pair(As[(m0+g  )*68 + kk + t + 4], ah[2], al[2]);
            tf32pair(As[(m0+g+8)*68 + kk + t + 4], ah[3], al[3]);
            uint32_t bh[8][2], bl[8][2];
#pragma unroll
            for (int nt = 0; nt < 8; ++nt) {
                tf32pair(Bs[((nt<<3)+g)*68 + kk + t    ], bh[nt][0], bl[nt][0]);
                tf32pair(Bs[((nt<<3)+g)*68 + kk + t + 4], bh[nt][1], bl[nt][1]);
            }
#pragma unroll
            for (int nt = 0; nt < 8; ++nt) mma8(acc[nt], ah, bh[nt][0], bh[nt][1]);
#pragma unroll
            for (int nt = 0; nt < 8; ++nt) mma8(acc[nt], ah, bl[nt][0], bl[nt][1]);
#pragma unroll
            for (int nt = 0; nt < 8; ++nt) mma8(acc[nt], al, bh[nt][0], bh[nt][1]);
        }
        if (s < 15) {
            fill(s + 1, (s + 1) & 1);    // writes the other buffer
            __syncthreads();
        }
    }

    // ---- epilogue: out = acc/1024 + X1_t ----
    const float inv = 1.0f / 1024.0f;
    const size_t base1 = ((size_t)b*NN + it0 + m0 + g)*DD;
    const size_t base2 = base1 + 8*DD;
#pragma unroll
    for (int nt = 0; nt < 8; ++nt) {
        const int col = (nt << 3) + (t << 1);
        float2 x1 = *reinterpret_cast<const float2*>(x1o + base1 + col);
        float2 o1;
        o1.x = acc[nt][0]*inv + x1.x;
        o1.y = acc[nt][1]*inv + x1.y;
        *reinterpret_cast<float2*>(x1o + base1 + col) = o1;
        float2 x2 = *reinterpret_cast<const float2*>(x1o + base2 + col);
        float2 o2;
        o2.x = acc[nt][2]*inv + x2.x;
        o2.y = acc[nt][3]*inv + x2.y;
        *reinterpret_cast<float2*>(x1o + base2 + col) = o2;
    }
}

// ---------------- launch ----------------
extern "C" void kernel_launch(void* const* d_in, const int* in_sizes, int n_in,
                              void* d_out, int out_size)
{
    const float* A      = (const float*)d_in[0];
    const float* X      = (const float*)d_in[1];
    const float* coeffs = (const float*)d_in[2];
    const float* wA1    = (const float*)d_in[3];
    const float* wA2    = (const float*)d_in[4];
    const float* w11    = (const float*)d_in[5];
    const float* w12    = (const float*)d_in[6];
    const float* w13    = (const float*)d_in[7];
    const float* w14    = (const float*)d_in[8];
    const float* w15    = (const float*)d_in[9];
    const float* w16    = (const float*)d_in[10];
    const float* w21    = (const float*)d_in[11];
    const float* w22    = (const float*)d_in[12];
    const float* w23    = (const float*)d_in[13];
    const float* w24    = (const float*)d_in[14];
    const float* w25    = (const float*)d_in[15];
    const float* w26    = (const float*)d_in[16];

    float* out = (float*)d_out;
    float* x1o = out + OUT_OFF;

    const int NODE_SMEM = (128*DD + 2*64*68) * (int)sizeof(float);  // 67584
    cudaFuncSetAttribute(k_node, cudaFuncAttributeMaxDynamicSharedMemorySize, NODE_SMEM);
    const int GEMM_SMEM = 2 * STG_F * (int)sizeof(float);           // 104448
    cudaFuncSetAttribute(k_gemm, cudaFuncAttributeMaxDynamicSharedMemorySize, GEMM_SMEM);

    k_row_stats  <<<2048, 256>>>(A, X, coeffs, wA1);
    k_batch_stats<<<16,   256>>>(X, coeffs, wA2, w12, w15, w16, w22, w25, w26);
    k_node       <<<dim3(8,16), 256, NODE_SMEM>>>(X, w11, w13, w14, w21, w23, w24, x1o);
    k_gemm       <<<dim3(8,16), 256, GEMM_SMEM>>>(A, coeffs, out, x1o);
}

// round 8
// speedup vs baseline: 1.3437x; 1.0100x over previous
#include <cuda_runtime.h>
#include <cuda_bf16.h>
#include <stdint.h>

#define NB 16
#define NN 1024
#define DD 64
#define OUT_OFF ((size_t)NB * NN * NN)

// ---------------- scratch (device globals; no allocation) ----------------
__device__ float g_rowmean[NB*NN];
__device__ float g_diag[NB*NN];
__device__ float g_r[NB*NN];            // c3*rowmean + c4*diag + p1
__device__ float g_s[NB];               // c1*mean_all + c2*mean_diag + p2
__device__ float g_pg1[NB*DD];
__device__ float g_pg2[NB*DD];
__device__ float g_BhiT[(size_t)NB*DD*NN];   // tf32-hi of X2_t^T: [b][e][k]
__device__ float g_BloT[(size_t)NB*DD*NN];   // tf32-lo residual

// ---------------- packed fp32x2 helpers (k_node) ----------------
__device__ __forceinline__ void fma2(unsigned long long &d,
                                     unsigned long long a,
                                     unsigned long long b) {
    asm("fma.rn.f32x2 %0, %1, %2, %0;" : "+l"(d) : "l"(a), "l"(b));
}
__device__ __forceinline__ float psum(unsigned long long v) {
    return __uint_as_float((unsigned)v) + __uint_as_float((unsigned)(v >> 32));
}

// ---------------- tf32 split ----------------
__device__ __forceinline__ void tf32pair(float v, uint32_t &h, uint32_t &l) {
    asm("cvt.rna.tf32.f32 %0, %1;" : "=r"(h) : "f"(v));
    float rmd = v - __uint_as_float(h);
    asm("cvt.rna.tf32.f32 %0, %1;" : "=r"(l) : "f"(rmd));
}
__device__ __forceinline__ void tf32split(float v, float &h, float &l) {
    uint32_t hb, lb;
    tf32pair(v, hb, lb);
    h = __uint_as_float(hb);
    l = __uint_as_float(lb);
}

// ---------------- m16n8k8 tf32 mma (HMMA, baseline PTX) ----------------
__device__ __forceinline__ void mma8(float* c, const uint32_t* a,
                                     uint32_t b0, uint32_t b1) {
    asm volatile(
        "mma.sync.aligned.m16n8k8.row.col.f32.tf32.tf32.f32 "
        "{%0,%1,%2,%3}, {%4,%5,%6,%7}, {%8,%9}, {%0,%1,%2,%3};"
        : "+f"(c[0]), "+f"(c[1]), "+f"(c[2]), "+f"(c[3])
        : "r"(a[0]), "r"(a[1]), "r"(a[2]), "r"(a[3]), "r"(b0), "r"(b1));
}

// ---------------- kernel 1: per-row stats (rowmean, diag, r) -------------
__global__ __launch_bounds__(256) void k_row_stats(
    const float* __restrict__ A, const float* __restrict__ X,
    const float* __restrict__ coeffs, const float* __restrict__ wA1)
{
    int gw = blockIdx.x * 8 + (threadIdx.x >> 5);   // global row 0..16383
    int lane = threadIdx.x & 31;
    const float4* arow = reinterpret_cast<const float4*>(A) + (size_t)gw * (NN/4);
    float s = 0.f;
#pragma unroll
    for (int w = 0; w < 8; ++w) {
        float4 v = arow[lane + (w << 5)];
        s += (v.x + v.y) + (v.z + v.w);
    }
    const float* xrow = X + (size_t)gw * DD;
    float p = xrow[lane] * wA1[lane] + xrow[lane+32] * wA1[lane+32];
#pragma unroll
    for (int o = 16; o; o >>= 1) {
        s += __shfl_xor_sync(0xffffffffu, s, o);
        p += __shfl_xor_sync(0xffffffffu, p, o);
    }
    if (lane == 0) {
        int i = gw & (NN-1);
        float d = A[(size_t)gw*NN + i];
        float rm = s * (1.f/NN);
        g_rowmean[gw] = rm;
        g_diag[gw]    = d;
        g_r[gw]       = coeffs[3]*rm + coeffs[4]*d + p;
    }
}

// ---------------- kernel 2: per-batch stats (s, pg1, pg2) ----------------
__global__ __launch_bounds__(256) void k_batch_stats(
    const float* __restrict__ X, const float* __restrict__ coeffs,
    const float* __restrict__ wA2,
    const float* __restrict__ w12, const float* __restrict__ w15, const float* __restrict__ w16,
    const float* __restrict__ w22, const float* __restrict__ w25, const float* __restrict__ w26)
{
    int b = blockIdx.x, t = threadIdx.x;
    __shared__ float red[256];
    __shared__ float sm_meanX[DD];
    __shared__ float sm_mall, sm_mdiag;

    float v1 = 0.f, v2 = 0.f;
    for (int i = t; i < NN; i += 256) { v1 += g_rowmean[b*NN+i]; v2 += g_diag[b*NN+i]; }
    red[t] = v1; __syncthreads();
    for (int o = 128; o > 0; o >>= 1) { if (t < o) red[t] += red[t+o]; __syncthreads(); }
    if (t == 0) sm_mall = red[0]*(1.f/NN);
    __syncthreads();
    red[t] = v2; __syncthreads();
    for (int o = 128; o > 0; o >>= 1) { if (t < o) red[t] += red[t+o]; __syncthreads(); }
    if (t == 0) sm_mdiag = red[0]*(1.f/NN);
    __syncthreads();

    int d = t & 63, g = t >> 6;
    float xs = 0.f;
    for (int j = g; j < NN; j += 4) xs += X[((size_t)b*NN + j)*DD + d];
    red[t] = xs; __syncthreads();
    if (g == 0) sm_meanX[d] = (red[d] + red[d+64] + red[d+128] + red[d+192]) * (1.f/NN);
    __syncthreads();

    float mall = sm_mall, mdiag = sm_mdiag;
    if (t == 0) {
        float p2 = 0.f;
        for (int k = 0; k < DD; ++k) p2 += sm_meanX[k]*wA2[k];
        g_s[b] = coeffs[1]*mall + coeffs[2]*mdiag + p2;
    } else if (t >= 64 && t < 128) {
        int e = t - 64;
        float a = 0.f;
        for (int k = 0; k < DD; ++k) a += sm_meanX[k]*w12[e*DD+k];
        g_pg1[b*DD+e] = a + mdiag*w15[e] + mall*w16[e];
    } else if (t >= 128 && t < 192) {
        int e = t - 128;
        float a = 0.f;
        for (int k = 0; k < DD; ++k) a += sm_meanX[k]*w22[e*DD+k];
        g_pg2[b*DD+e] = a + mdiag*w25[e] + mall*w26[e];
    }
}

// ---------------- kernel 3: node transforms X1_t, X2_t^T (hi/lo) ---------
// dynamic smem: Xs[128*64] | W1[64*68] | W2[64*68]  (67584 B)
__global__ __launch_bounds__(256) void k_node(
    const float* __restrict__ X,
    const float* __restrict__ w11, const float* __restrict__ w13, const float* __restrict__ w14,
    const float* __restrict__ w21, const float* __restrict__ w23, const float* __restrict__ w24,
    float* __restrict__ x1o)
{
    extern __shared__ __align__(16) float sm[];
    float* Xs = sm;               // [128][64]
    float* W1 = sm + 128*DD;      // [64][68]
    float* W2 = W1 + 64*68;       // [64][68]

    const int b = blockIdx.y;
    const int it0 = blockIdx.x << 7;    // 128 rows per block
    const int tid = threadIdx.x;
    const int c4 = tid & 15, r0 = tid >> 4;   // r0 0..15
    const int ci = c4 << 2;

    const float* Xb = X + ((size_t)b*NN + it0)*DD;
#pragma unroll
    for (int t = 0; t < 8; ++t) {
        int row = r0 + (t << 4);
        *reinterpret_cast<float4*>(Xs + row*DD + ci) =
            *reinterpret_cast<const float4*>(Xb + (size_t)row*DD + ci);
    }
#pragma unroll
    for (int t = 0; t < 4; ++t) {
        int e = r0 + (t << 4);
        *reinterpret_cast<float4*>(W1 + e*68 + ci) = *reinterpret_cast<const float4*>(w11 + e*DD + ci);
        *reinterpret_cast<float4*>(W2 + e*68 + ci) = *reinterpret_cast<const float4*>(w21 + e*DD + ci);
    }
    __syncthreads();

    const int tx = tid & 15, ty = tid >> 4;
    const int e0 = tx << 2, i0 = ty << 3;   // i0 0..120

    float rmv[8], dgv[8];
#pragma unroll
    for (int r = 0; r < 8; ++r) {
        int row = b*NN + it0 + i0 + r;
        rmv[r] = g_rowmean[row];
        dgv[r] = g_diag[row];
    }

    unsigned long long acc[8][4];

    // ---- pass 1: X1_t -> x1o ----
#pragma unroll
    for (int r = 0; r < 8; ++r)
#pragma unroll
        for (int q = 0; q < 4; ++q) acc[r][q] = 0ull;
#pragma unroll 2
    for (int d = 0; d < DD; d += 4) {
        ulonglong2 a[8];
#pragma unroll
        for (int r = 0; r < 8; ++r)
            a[r] = *reinterpret_cast<const ulonglong2*>(Xs + (i0+r)*DD + d);
#pragma unroll
        for (int q = 0; q < 4; ++q) {
            ulonglong2 bv = *reinterpret_cast<const ulonglong2*>(W1 + (e0+q)*68 + d);
#pragma unroll
            for (int r = 0; r < 8; ++r) { fma2(acc[r][q], a[r].x, bv.x); fma2(acc[r][q], a[r].y, bv.y); }
        }
    }
    {
        float4 wc = *reinterpret_cast<const float4*>(w13 + e0);
        float4 wd = *reinterpret_cast<const float4*>(w14 + e0);
        float4 pg = *reinterpret_cast<const float4*>(g_pg1 + b*DD + e0);
#pragma unroll
        for (int r = 0; r < 8; ++r) {
            float4 o;
            o.x = psum(acc[r][0]) + rmv[r]*wc.x + dgv[r]*wd.x + pg.x;
            o.y = psum(acc[r][1]) + rmv[r]*wc.y + dgv[r]*wd.y + pg.y;
            o.z = psum(acc[r][2]) + rmv[r]*wc.z + dgv[r]*wd.z + pg.z;
            o.w = psum(acc[r][3]) + rmv[r]*wc.w + dgv[r]*wd.w + pg.w;
            *reinterpret_cast<float4*>(x1o + ((size_t)b*NN + it0 + i0 + r)*DD + e0) = o;
        }
    }

    // ---- pass 2: X2_t -> registers, then SMEM-bounce transpose ----
#pragma unroll
    for (int r = 0; r < 8; ++r)
#pragma unroll
        for (int q = 0; q < 4; ++q) acc[r][q] = 0ull;
#pragma unroll 2
    for (int d = 0; d < DD; d += 4) {
        ulonglong2 a[8];
#pragma unroll
        for (int r = 0; r < 8; ++r)
            a[r] = *reinterpret_cast<const ulonglong2*>(Xs + (i0+r)*DD + d);
#pragma unroll
        for (int q = 0; q < 4; ++q) {
            ulonglong2 bv = *reinterpret_cast<const ulonglong2*>(W2 + (e0+q)*68 + d);
#pragma unroll
            for (int r = 0; r < 8; ++r) { fma2(acc[r][q], a[r].x, bv.x); fma2(acc[r][q], a[r].y, bv.y); }
        }
    }
    float4 o2v[8];
    {
        float4 wc = *reinterpret_cast<const float4*>(w23 + e0);
        float4 wd = *reinterpret_cast<const float4*>(w24 + e0);
        float4 pg = *reinterpret_cast<const float4*>(g_pg2 + b*DD + e0);
#pragma unroll
        for (int r = 0; r < 8; ++r) {
            o2v[r].x = psum(acc[r][0]) + rmv[r]*wc.x + dgv[r]*wd.x + pg.x;
            o2v[r].y = psum(acc[r][1]) + rmv[r]*wc.y + dgv[r]*wd.y + pg.y;
            o2v[r].z = psum(acc[r][2]) + rmv[r]*wc.z + dgv[r]*wd.z + pg.z;
            o2v[r].w = psum(acc[r][3]) + rmv[r]*wc.w + dgv[r]*wd.w + pg.w;
        }
    }
    __syncthreads();   // all reads of Xs done -> reuse as transpose buffer
#pragma unroll
    for (int r = 0; r < 8; ++r)
        *reinterpret_cast<float4*>(Xs + (i0+r)*DD + e0) = o2v[r];
    __syncthreads();

    // transposed hi/lo write: g_BhiT/g_BloT [b][e][j]
    const int e = tid & 63, rc = tid >> 6;   // rc 0..3
#pragma unroll
    for (int rr = 0; rr < 8; ++rr) {
        int rowl = (rc << 5) + (rr << 2);
        float4 h, l;
        tf32split(Xs[(rowl+0)*DD + e], h.x, l.x);
        tf32split(Xs[(rowl+1)*DD + e], h.y, l.y);
        tf32split(Xs[(rowl+2)*DD + e], h.z, l.z);
        tf32split(Xs[(rowl+3)*DD + e], h.w, l.w);
        size_t off = ((size_t)b*DD + e)*NN + it0 + rowl;
        *reinterpret_cast<float4*>(g_BhiT + off) = h;
        *reinterpret_cast<float4*>(g_BloT + off) = l;
    }
}

// ---------------- kernel 4: HMMA tf32 GEMM (3xTF32, mma.sync) ------------
// 256 threads, 128x64 tile, KC=64, double-buffered smem: A fp32 + B hi/lo
// pre-split (no in-loop B cvt). Warp tile 32x32 (2 m-tiles x 4 n-tiles).
#define STG_F (128*68 + 2*64*68)   // 17408 floats per stage
__global__ __launch_bounds__(256, 1) void k_gemm(
    const float* __restrict__ A, const float* __restrict__ coeffs,
    float* __restrict__ At, float* __restrict__ x1o)
{
    extern __shared__ __align__(16) float sm[];
    const int tid = threadIdx.x;
    const int wid = tid >> 5, lane = tid & 31;
    const int b = blockIdx.y, it0 = blockIdx.x << 7;

    // loader coords
    const int rb = tid >> 4;            // 0..15 (A rows rb+16i)
    const int ci = (tid & 15) << 2;     // 0..60
    const int eb = tid >> 2;            // 0..63 (B row)
    const int kq = (tid & 3) << 4;      // 0,16,32,48

    const float c0 = coeffs[0];
    const float sbv = g_s[b];
    float rloc[8];
#pragma unroll
    for (int i = 0; i < 8; ++i) rloc[i] = sbv + g_r[b*NN + it0 + rb + (i << 4)];

    const float* Ab = A  + ((size_t)b*NN + it0)*NN;
    float*       Ob = At + ((size_t)b*NN + it0)*NN;
    const float* Bh = g_BhiT + (size_t)b*DD*NN;
    const float* Bl = g_BloT + (size_t)b*DD*NN;

    float acc[2][4][4];
#pragma unroll
    for (int mt = 0; mt < 2; ++mt)
#pragma unroll
        for (int nt = 0; nt < 4; ++nt)
#pragma unroll
            for (int q = 0; q < 4; ++q) acc[mt][nt][q] = 0.f;

    float4 Ar[8], Bhr[4], Blr[4], rjv;
    auto fetch = [&](int s) {
        const int k0 = s << 6;
        rjv = *reinterpret_cast<const float4*>(g_r + b*NN + k0 + ci);
#pragma unroll
        for (int i = 0; i < 8; ++i)
            Ar[i] = *reinterpret_cast<const float4*>(Ab + (size_t)(rb + (i << 4))*NN + k0 + ci);
#pragma unroll
        for (int q = 0; q < 4; ++q) {
            Bhr[q] = *reinterpret_cast<const float4*>(Bh + (size_t)eb*NN + k0 + kq + (q << 2));
            Blr[q] = *reinterpret_cast<const float4*>(Bl + (size_t)eb*NN + k0 + kq + (q << 2));
        }
    };
    auto fill = [&](int s, int buf) {
        const int k0 = s << 6;
        float* As  = sm + buf * STG_F;
        float* Bsh = As + 128*68;
        float* Bsl = Bsh + 64*68;
#pragma unroll
        for (int i = 0; i < 8; ++i) {
            int row = rb + (i << 4);
            float4 atv;
            atv.x = fmaf(c0, Ar[i].x, rloc[i] + rjv.x);
            atv.y = fmaf(c0, Ar[i].y, rloc[i] + rjv.y);
            atv.z = fmaf(c0, Ar[i].z, rloc[i] + rjv.z);
            atv.w = fmaf(c0, Ar[i].w, rloc[i] + rjv.w);
            *reinterpret_cast<float4*>(Ob + (size_t)row*NN + k0 + ci) = atv;   // A_t out
            *reinterpret_cast<float4*>(As + row*68 + ci) = atv;
        }
#pragma unroll
        for (int q = 0; q < 4; ++q) {
            *reinterpret_cast<float4*>(Bsh + eb*68 + kq + (q << 2)) = Bhr[q];
            *reinterpret_cast<float4*>(Bsl + eb*68 + kq + (q << 2)) = Blr[q];
        }
    };

    const int g = lane >> 2, t = lane & 3;
    const int m0 = (wid & 3) << 5;       // 4 m-groups of 32 rows
    const int e0 = (wid >> 2) << 5;      // 2 e-groups of 32 cols

    fetch(0);
    fill(0, 0);
    __syncthreads();

    for (int s = 0; s < 16; ++s) {
        if (s < 15) fetch(s + 1);        // LDG in flight behind MMAs
        const float* As  = sm + (s & 1) * STG_F;
        const float* Bsh = As + 128*68;
        const float* Bsl = Bsh + 64*68;
#pragma unroll
        for (int ks = 0; ks < 8; ++ks) {
            const int kk = ks << 3;
            uint32_t ah[2][4], al[2][4];
#pragma unroll
            for (int mt = 0; mt < 2; ++mt) {
                const int rowb = m0 + (mt << 4);
                tf32pair(As[(rowb+g  )*68 + kk + t    ], ah[mt][0], al[mt][0]);
                tf32pair(As[(rowb+g+8)*68 + kk + t    ], ah[mt][1], al[mt][1]);
                tf32pair(As[(rowb+g  )*68 + kk + t + 4], ah[mt][2], al[mt][2]);
                tf32pair(As[(rowb+g+8)*68 + kk + t + 4], ah[mt][3], al[mt][3]);
            }
            uint32_t bh[4][2], bl[4][2];
#pragma unroll
            for (int nt = 0; nt < 4; ++nt) {
                const int er = (e0 + (nt << 3) + g)*68 + kk + t;
                bh[nt][0] = __float_as_uint(Bsh[er    ]);
                bh[nt][1] = __float_as_uint(Bsh[er + 4]);
                bl[nt][0] = __float_as_uint(Bsl[er    ]);
                bl[nt][1] = __float_as_uint(Bsl[er + 4]);
            }
#pragma unroll
            for (int mt = 0; mt < 2; ++mt)
#pragma unroll
                for (int nt = 0; nt < 4; ++nt) {
                    mma8(acc[mt][nt], ah[mt], bh[nt][0], bh[nt][1]);
                    mma8(acc[mt][nt], ah[mt], bl[nt][0], bl[nt][1]);
                    mma8(acc[mt][nt], al[mt], bh[nt][0], bh[nt][1]);
                }
        }
        if (s < 15) {
            fill(s + 1, (s + 1) & 1);    // writes the other buffer
            __syncthreads();
        }
    }

    // ---- epilogue: out = acc/1024 + X1_t ----
    const float inv = 1.0f / 1024.0f;
#pragma unroll
    for (int mt = 0; mt < 2; ++mt) {
        const int row1 = it0 + m0 + (mt << 4) + g;
        const size_t b1 = ((size_t)b*NN + row1)*DD;
        const size_t b2 = b1 + 8*DD;
#pragma unroll
        for (int nt = 0; nt < 4; ++nt) {
            const int col = e0 + (nt << 3) + (t << 1);
            float2 x1 = *reinterpret_cast<const float2*>(x1o + b1 + col);
            float2 o1;
            o1.x = acc[mt][nt][0]*inv + x1.x;
            o1.y = acc[mt][nt][1]*inv + x1.y;
            *reinterpret_cast<float2*>(x1o + b1 + col) = o1;
            float2 x2 = *reinterpret_cast<const float2*>(x1o + b2 + col);
            float2 o2;
            o2.x = acc[mt][nt][2]*inv + x2.x;
            o2.y = acc[mt][nt][3]*inv + x2.y;
            *reinterpret_cast<float2*>(x1o + b2 + col) = o2;
        }
    }
}

// ---------------- launch ----------------
extern "C" void kernel_launch(void* const* d_in, const int* in_sizes, int n_in,
                              void* d_out, int out_size)
{
    const float* A      = (const float*)d_in[0];
    const float* X      = (const float*)d_in[1];
    const float* coeffs = (const float*)d_in[2];
    const float* wA1    = (const float*)d_in[3];
    const float* wA2    = (const float*)d_in[4];
    const float* w11    = (const float*)d_in[5];
    const float* w12    = (const float*)d_in[6];
    const float* w13    = (const float*)d_in[7];
    const float* w14    = (const float*)d_in[8];
    const float* w15    = (const float*)d_in[9];
    const float* w16    = (const float*)d_in[10];
    const float* w21    = (const float*)d_in[11];
    const float* w22    = (const float*)d_in[12];
    const float* w23    = (const float*)d_in[13];
    const float* w24    = (const float*)d_in[14];
    const float* w25    = (const float*)d_in[15];
    const float* w26    = (const float*)d_in[16];

    float* out = (float*)d_out;
    float* x1o = out + OUT_OFF;

    const int NODE_SMEM = (128*DD + 2*64*68) * (int)sizeof(float);  // 67584
    cudaFuncSetAttribute(k_node, cudaFuncAttributeMaxDynamicSharedMemorySize, NODE_SMEM);
    const int GEMM_SMEM = 2 * STG_F * (int)sizeof(float);           // 139264
    cudaFuncSetAttribute(k_gemm, cudaFuncAttributeMaxDynamicSharedMemorySize, GEMM_SMEM);

    k_row_stats  <<<2048, 256>>>(A, X, coeffs, wA1);
    k_batch_stats<<<16,   256>>>(X, coeffs, wA2, w12, w15, w16, w22, w25, w26);
    k_node       <<<dim3(8,16), 256, NODE_SMEM>>>(X, w11, w13, w14, w21, w23, w24, x1o);
    k_gemm       <<<dim3(8,16), 256, GEMM_SMEM>>>(A, coeffs, out, x1o);
}

// round 9
// speedup vs baseline: 1.3515x; 1.0058x over previous
#include <cuda_runtime.h>
#include <cuda_bf16.h>
#include <stdint.h>

#define NB 16
#define NN 1024
#define DD 64
#define OUT_OFF ((size_t)NB * NN * NN)

// ---------------- scratch (device globals; no allocation) ----------------
__device__ float g_rowmean[NB*NN];
__device__ float g_diag[NB*NN];
__device__ float g_r[NB*NN];            // c3*rowmean + c4*diag + p1
__device__ float g_s[NB];               // c1*mean_all + c2*mean_diag + p2
__device__ float g_pg1[NB*DD];
__device__ float g_pg2[NB*DD];
__device__ float g_BhiT[(size_t)NB*DD*NN];   // tf32-hi of X2_t^T: [b][e][k]
__device__ float g_BloT[(size_t)NB*DD*NN];   // tf32-lo residual

// ---------------- packed fp32x2 helpers (k_node) ----------------
__device__ __forceinline__ void fma2(unsigned long long &d,
                                     unsigned long long a,
                                     unsigned long long b) {
    asm("fma.rn.f32x2 %0, %1, %2, %0;" : "+l"(d) : "l"(a), "l"(b));
}
__device__ __forceinline__ float psum(unsigned long long v) {
    return __uint_as_float((unsigned)v) + __uint_as_float((unsigned)(v >> 32));
}

// ---------------- tf32 split ----------------
__device__ __forceinline__ void tf32pair(float v, uint32_t &h, uint32_t &l) {
    asm("cvt.rna.tf32.f32 %0, %1;" : "=r"(h) : "f"(v));
    float rmd = v - __uint_as_float(h);
    asm("cvt.rna.tf32.f32 %0, %1;" : "=r"(l) : "f"(rmd));
}
__device__ __forceinline__ void tf32split(float v, float &h, float &l) {
    uint32_t hb, lb;
    tf32pair(v, hb, lb);
    h = __uint_as_float(hb);
    l = __uint_as_float(lb);
}

// ---------------- m16n8k8 tf32 mma (HMMA, baseline PTX) ----------------
// NOT volatile: pure register op, lets ptxas schedule/pipeline freely.
__device__ __forceinline__ void mma8(float* c, const uint32_t* a,
                                     uint32_t b0, uint32_t b1) {
    asm("mma.sync.aligned.m16n8k8.row.col.f32.tf32.tf32.f32 "
        "{%0,%1,%2,%3}, {%4,%5,%6,%7}, {%8,%9}, {%0,%1,%2,%3};"
        : "+f"(c[0]), "+f"(c[1]), "+f"(c[2]), "+f"(c[3])
        : "r"(a[0]), "r"(a[1]), "r"(a[2]), "r"(a[3]), "r"(b0), "r"(b1));
}

// ---------------- kernel 1: per-row stats (rowmean, diag, r) -------------
__global__ __launch_bounds__(256) void k_row_stats(
    const float* __restrict__ A, const float* __restrict__ X,
    const float* __restrict__ coeffs, const float* __restrict__ wA1)
{
    int gw = blockIdx.x * 8 + (threadIdx.x >> 5);   // global row 0..16383
    int lane = threadIdx.x & 31;
    const float4* arow = reinterpret_cast<const float4*>(A) + (size_t)gw * (NN/4);
    float s = 0.f;
#pragma unroll
    for (int w = 0; w < 8; ++w) {
        float4 v = arow[lane + (w << 5)];
        s += (v.x + v.y) + (v.z + v.w);
    }
    const float* xrow = X + (size_t)gw * DD;
    float p = xrow[lane] * wA1[lane] + xrow[lane+32] * wA1[lane+32];
#pragma unroll
    for (int o = 16; o; o >>= 1) {
        s += __shfl_xor_sync(0xffffffffu, s, o);
        p += __shfl_xor_sync(0xffffffffu, p, o);
    }
    if (lane == 0) {
        int i = gw & (NN-1);
        float d = A[(size_t)gw*NN + i];
        float rm = s * (1.f/NN);
        g_rowmean[gw] = rm;
        g_diag[gw]    = d;
        g_r[gw]       = coeffs[3]*rm + coeffs[4]*d + p;
    }
}

// ---------------- kernel 2: per-batch stats (s, pg1, pg2) ----------------
__global__ __launch_bounds__(256) void k_batch_stats(
    const float* __restrict__ X, const float* __restrict__ coeffs,
    const float* __restrict__ wA2,
    const float* __restrict__ w12, const float* __restrict__ w15, const float* __restrict__ w16,
    const float* __restrict__ w22, const float* __restrict__ w25, const float* __restrict__ w26)
{
    int b = blockIdx.x, t = threadIdx.x;
    __shared__ float red[256];
    __shared__ float sm_meanX[DD];
    __shared__ float sm_mall, sm_mdiag;

    float v1 = 0.f, v2 = 0.f;
    for (int i = t; i < NN; i += 256) { v1 += g_rowmean[b*NN+i]; v2 += g_diag[b*NN+i]; }
    red[t] = v1; __syncthreads();
    for (int o = 128; o > 0; o >>= 1) { if (t < o) red[t] += red[t+o]; __syncthreads(); }
    if (t == 0) sm_mall = red[0]*(1.f/NN);
    __syncthreads();
    red[t] = v2; __syncthreads();
    for (int o = 128; o > 0; o >>= 1) { if (t < o) red[t] += red[t+o]; __syncthreads(); }
    if (t == 0) sm_mdiag = red[0]*(1.f/NN);
    __syncthreads();

    int d = t & 63, g = t >> 6;
    float xs = 0.f;
    for (int j = g; j < NN; j += 4) xs += X[((size_t)b*NN + j)*DD + d];
    red[t] = xs; __syncthreads();
    if (g == 0) sm_meanX[d] = (red[d] + red[d+64] + red[d+128] + red[d+192]) * (1.f/NN);
    __syncthreads();

    float mall = sm_mall, mdiag = sm_mdiag;
    if (t == 0) {
        float p2 = 0.f;
        for (int k = 0; k < DD; ++k) p2 += sm_meanX[k]*wA2[k];
        g_s[b] = coeffs[1]*mall + coeffs[2]*mdiag + p2;
    } else if (t >= 64 && t < 128) {
        int e = t - 64;
        float a = 0.f;
        for (int k = 0; k < DD; ++k) a += sm_meanX[k]*w12[e*DD+k];
        g_pg1[b*DD+e] = a + mdiag*w15[e] + mall*w16[e];
    } else if (t >= 128 && t < 192) {
        int e = t - 128;
        float a = 0.f;
        for (int k = 0; k < DD; ++k) a += sm_meanX[k]*w22[e*DD+k];
        g_pg2[b*DD+e] = a + mdiag*w25[e] + mall*w26[e];
    }
}

// ---------------- kernel 3: node transforms X1_t, X2_t^T (hi/lo) ---------
// dynamic smem: Xs[128*64] | W1[64*68] | W2[64*68]  (67584 B)
__global__ __launch_bounds__(256) void k_node(
    const float* __restrict__ X,
    const float* __restrict__ w11, const float* __restrict__ w13, const float* __restrict__ w14,
    const float* __restrict__ w21, const float* __restrict__ w23, const float* __restrict__ w24,
    float* __restrict__ x1o)
{
    extern __shared__ __align__(16) float sm[];
    float* Xs = sm;               // [128][64]
    float* W1 = sm + 128*DD;      // [64][68]
    float* W2 = W1 + 64*68;       // [64][68]

    const int b = blockIdx.y;
    const int it0 = blockIdx.x << 7;    // 128 rows per block
    const int tid = threadIdx.x;
    const int c4 = tid & 15, r0 = tid >> 4;   // r0 0..15
    const int ci = c4 << 2;

    const float* Xb = X + ((size_t)b*NN + it0)*DD;
#pragma unroll
    for (int t = 0; t < 8; ++t) {
        int row = r0 + (t << 4);
        *reinterpret_cast<float4*>(Xs + row*DD + ci) =
            *reinterpret_cast<const float4*>(Xb + (size_t)row*DD + ci);
    }
#pragma unroll
    for (int t = 0; t < 4; ++t) {
        int e = r0 + (t << 4);
        *reinterpret_cast<float4*>(W1 + e*68 + ci) = *reinterpret_cast<const float4*>(w11 + e*DD + ci);
        *reinterpret_cast<float4*>(W2 + e*68 + ci) = *reinterpret_cast<const float4*>(w21 + e*DD + ci);
    }
    __syncthreads();

    const int tx = tid & 15, ty = tid >> 4;
    const int e0 = tx << 2, i0 = ty << 3;   // i0 0..120

    float rmv[8], dgv[8];
#pragma unroll
    for (int r = 0; r < 8; ++r) {
        int row = b*NN + it0 + i0 + r;
        rmv[r] = g_rowmean[row];
        dgv[r] = g_diag[row];
    }

    unsigned long long acc[8][4];

    // ---- pass 1: X1_t -> x1o ----
#pragma unroll
    for (int r = 0; r < 8; ++r)
#pragma unroll
        for (int q = 0; q < 4; ++q) acc[r][q] = 0ull;
#pragma unroll 2
    for (int d = 0; d < DD; d += 4) {
        ulonglong2 a[8];
#pragma unroll
        for (int r = 0; r < 8; ++r)
            a[r] = *reinterpret_cast<const ulonglong2*>(Xs + (i0+r)*DD + d);
#pragma unroll
        for (int q = 0; q < 4; ++q) {
            ulonglong2 bv = *reinterpret_cast<const ulonglong2*>(W1 + (e0+q)*68 + d);
#pragma unroll
            for (int r = 0; r < 8; ++r) { fma2(acc[r][q], a[r].x, bv.x); fma2(acc[r][q], a[r].y, bv.y); }
        }
    }
    {
        float4 wc = *reinterpret_cast<const float4*>(w13 + e0);
        float4 wd = *reinterpret_cast<const float4*>(w14 + e0);
        float4 pg = *reinterpret_cast<const float4*>(g_pg1 + b*DD + e0);
#pragma unroll
        for (int r = 0; r < 8; ++r) {
            float4 o;
            o.x = psum(acc[r][0]) + rmv[r]*wc.x + dgv[r]*wd.x + pg.x;
            o.y = psum(acc[r][1]) + rmv[r]*wc.y + dgv[r]*wd.y + pg.y;
            o.z = psum(acc[r][2]) + rmv[r]*wc.z + dgv[r]*wd.z + pg.z;
            o.w = psum(acc[r][3]) + rmv[r]*wc.w + dgv[r]*wd.w + pg.w;
            *reinterpret_cast<float4*>(x1o + ((size_t)b*NN + it0 + i0 + r)*DD + e0) = o;
        }
    }

    // ---- pass 2: X2_t -> registers, then SMEM-bounce transpose ----
#pragma unroll
    for (int r = 0; r < 8; ++r)
#pragma unroll
        for (int q = 0; q < 4; ++q) acc[r][q] = 0ull;
#pragma unroll 2
    for (int d = 0; d < DD; d += 4) {
        ulonglong2 a[8];
#pragma unroll
        for (int r = 0; r < 8; ++r)
            a[r] = *reinterpret_cast<const ulonglong2*>(Xs + (i0+r)*DD + d);
#pragma unroll
        for (int q = 0; q < 4; ++q) {
            ulonglong2 bv = *reinterpret_cast<const ulonglong2*>(W2 + (e0+q)*68 + d);
#pragma unroll
            for (int r = 0; r < 8; ++r) { fma2(acc[r][q], a[r].x, bv.x); fma2(acc[r][q], a[r].y, bv.y); }
        }
    }
    float4 o2v[8];
    {
        float4 wc = *reinterpret_cast<const float4*>(w23 + e0);
        float4 wd = *reinterpret_cast<const float4*>(w24 + e0);
        float4 pg = *reinterpret_cast<const float4*>(g_pg2 + b*DD + e0);
#pragma unroll
        for (int r = 0; r < 8; ++r) {
            o2v[r].x = psum(acc[r][0]) + rmv[r]*wc.x + dgv[r]*wd.x + pg.x;
            o2v[r].y = psum(acc[r][1]) + rmv[r]*wc.y + dgv[r]*wd.y + pg.y;
            o2v[r].z = psum(acc[r][2]) + rmv[r]*wc.z + dgv[r]*wd.z + pg.z;
            o2v[r].w = psum(acc[r][3]) + rmv[r]*wc.w + dgv[r]*wd.w + pg.w;
        }
    }
    __syncthreads();   // all reads of Xs done -> reuse as transpose buffer
#pragma unroll
    for (int r = 0; r < 8; ++r)
        *reinterpret_cast<float4*>(Xs + (i0+r)*DD + e0) = o2v[r];
    __syncthreads();

    // transposed hi/lo write: g_BhiT/g_BloT [b][e][j]
    const int e = tid & 63, rc = tid >> 6;   // rc 0..3
#pragma unroll
    for (int rr = 0; rr < 8; ++rr) {
        int rowl = (rc << 5) + (rr << 2);
        float4 h, l;
        tf32split(Xs[(rowl+0)*DD + e], h.x, l.x);
        tf32split(Xs[(rowl+1)*DD + e], h.y, l.y);
        tf32split(Xs[(rowl+2)*DD + e], h.z, l.z);
        tf32split(Xs[(rowl+3)*DD + e], h.w, l.w);
        size_t off = ((size_t)b*DD + e)*NN + it0 + rowl;
        *reinterpret_cast<float4*>(g_BhiT + off) = h;
        *reinterpret_cast<float4*>(g_BloT + off) = l;
    }
}

// ---------------- kernel 4: HMMA tf32 GEMM (3xTF32, mma.sync) ------------
// 256 threads, 128x64 tile, KC=64, double-buffered smem: A fp32 + B hi/lo.
// Warp tile 32x32. MMA emission reordered pass-major (hh x8, hl x8, lh x8)
// so consecutive MMAs hit distinct accumulators (no RAW stall chains).
#define STG_F (128*68 + 2*64*68)   // 17408 floats per stage
__global__ __launch_bounds__(256, 1) void k_gemm(
    const float* __restrict__ A, const float* __restrict__ coeffs,
    float* __restrict__ At, float* __restrict__ x1o)
{
    extern __shared__ __align__(16) float sm[];
    const int tid = threadIdx.x;
    const int wid = tid >> 5, lane = tid & 31;
    const int b = blockIdx.y, it0 = blockIdx.x << 7;

    // loader coords
    const int rb = tid >> 4;            // 0..15 (A rows rb+16i)
    const int ci = (tid & 15) << 2;     // 0..60
    const int eb = tid >> 2;            // 0..63 (B row)
    const int kq = (tid & 3) << 4;      // 0,16,32,48

    const float c0 = coeffs[0];
    const float sbv = g_s[b];
    float rloc[8];
#pragma unroll
    for (int i = 0; i < 8; ++i) rloc[i] = sbv + g_r[b*NN + it0 + rb + (i << 4)];

    const float* Ab = A  + ((size_t)b*NN + it0)*NN;
    float*       Ob = At + ((size_t)b*NN + it0)*NN;
    const float* Bh = g_BhiT + (size_t)b*DD*NN;
    const float* Bl = g_BloT + (size_t)b*DD*NN;

    float acc[2][4][4];
#pragma unroll
    for (int mt = 0; mt < 2; ++mt)
#pragma unroll
        for (int nt = 0; nt < 4; ++nt)
#pragma unroll
            for (int q = 0; q < 4; ++q) acc[mt][nt][q] = 0.f;

    float4 Ar[8], Bhr[4], Blr[4], rjv;
    auto fetch = [&](int s) {
        const int k0 = s << 6;
        rjv = *reinterpret_cast<const float4*>(g_r + b*NN + k0 + ci);
#pragma unroll
        for (int i = 0; i < 8; ++i)
            Ar[i] = *reinterpret_cast<const float4*>(Ab + (size_t)(rb + (i << 4))*NN + k0 + ci);
#pragma unroll
        for (int q = 0; q < 4; ++q) {
            Bhr[q] = *reinterpret_cast<const float4*>(Bh + (size_t)eb*NN + k0 + kq + (q << 2));
            Blr[q] = *reinterpret_cast<const float4*>(Bl + (size_t)eb*NN + k0 + kq + (q << 2));
        }
    };
    auto fill = [&](int s, int buf) {
        const int k0 = s << 6;
        float* As  = sm + buf * STG_F;
        float* Bsh = As + 128*68;
        float* Bsl = Bsh + 64*68;
#pragma unroll
        for (int i = 0; i < 8; ++i) {
            int row = rb + (i << 4);
            float4 atv;
            atv.x = fmaf(c0, Ar[i].x, rloc[i] + rjv.x);
            atv.y = fmaf(c0, Ar[i].y, rloc[i] + rjv.y);
            atv.z = fmaf(c0, Ar[i].z, rloc[i] + rjv.z);
            atv.w = fmaf(c0, Ar[i].w, rloc[i] + rjv.w);
            *reinterpret_cast<float4*>(Ob + (size_t)row*NN + k0 + ci) = atv;   // A_t out
            *reinterpret_cast<float4*>(As + row*68 + ci) = atv;
        }
#pragma unroll
        for (int q = 0; q < 4; ++q) {
            *reinterpret_cast<float4*>(Bsh + eb*68 + kq + (q << 2)) = Bhr[q];
            *reinterpret_cast<float4*>(Bsl + eb*68 + kq + (q << 2)) = Blr[q];
        }
    };

    const int g = lane >> 2, t = lane & 3;
    const int m0 = (wid & 3) << 5;       // 4 m-groups of 32 rows
    const int e0 = (wid >> 2) << 5;      // 2 e-groups of 32 cols

    fetch(0);
    fill(0, 0);
    __syncthreads();

    for (int s = 0; s < 16; ++s) {
        if (s < 15) fetch(s + 1);        // LDG in flight behind MMAs
        const float* As  = sm + (s & 1) * STG_F;
        const float* Bsh = As + 128*68;
        const float* Bsl = Bsh + 64*68;
#pragma unroll
        for (int ks = 0; ks < 8; ++ks) {
            const int kk = ks << 3;
            uint32_t ah[2][4], al[2][4];
#pragma unroll
            for (int mt = 0; mt < 2; ++mt) {
                const int rowb = m0 + (mt << 4);
                tf32pair(As[(rowb+g  )*68 + kk + t    ], ah[mt][0], al[mt][0]);
                tf32pair(As[(rowb+g+8)*68 + kk + t    ], ah[mt][1], al[mt][1]);
                tf32pair(As[(rowb+g  )*68 + kk + t + 4], ah[mt][2], al[mt][2]);
                tf32pair(As[(rowb+g+8)*68 + kk + t + 4], ah[mt][3], al[mt][3]);
            }
            uint32_t bh[4][2], bl[4][2];
#pragma unroll
            for (int nt = 0; nt < 4; ++nt) {
                const int er = (e0 + (nt << 3) + g)*68 + kk + t;
                bh[nt][0] = __float_as_uint(Bsh[er    ]);
                bh[nt][1] = __float_as_uint(Bsh[er + 4]);
                bl[nt][0] = __float_as_uint(Bsl[er    ]);
                bl[nt][1] = __float_as_uint(Bsl[er + 4]);
            }
            // pass-major order: consecutive MMAs -> distinct accumulators
#pragma unroll
            for (int mt = 0; mt < 2; ++mt)
#pragma unroll
                for (int nt = 0; nt < 4; ++nt)
                    mma8(acc[mt][nt], ah[mt], bh[nt][0], bh[nt][1]);
#pragma unroll
            for (int mt = 0; mt < 2; ++mt)
#pragma unroll
                for (int nt = 0; nt < 4; ++nt)
                    mma8(acc[mt][nt], ah[mt], bl[nt][0], bl[nt][1]);
#pragma unroll
            for (int mt = 0; mt < 2; ++mt)
#pragma unroll
                for (int nt = 0; nt < 4; ++nt)
                    mma8(acc[mt][nt], al[mt], bh[nt][0], bh[nt][1]);
        }
        if (s < 15) {
            fill(s + 1, (s + 1) & 1);    // writes the other buffer
            __syncthreads();
        }
    }

    // ---- epilogue: out = acc/1024 + X1_t ----
    const float inv = 1.0f / 1024.0f;
#pragma unroll
    for (int mt = 0; mt < 2; ++mt) {
        const int row1 = it0 + m0 + (mt << 4) + g;
        const size_t b1 = ((size_t)b*NN + row1)*DD;
        const size_t b2 = b1 + 8*DD;
#pragma unroll
        for (int nt = 0; nt < 4; ++nt) {
            const int col = e0 + (nt << 3) + (t << 1);
            float2 x1 = *reinterpret_cast<const float2*>(x1o + b1 + col);
            float2 o1;
            o1.x = acc[mt][nt][0]*inv + x1.x;
            o1.y = acc[mt][nt][1]*inv + x1.y;
            *reinterpret_cast<float2*>(x1o + b1 + col) = o1;
            float2 x2 = *reinterpret_cast<const float2*>(x1o + b2 + col);
            float2 o2;
            o2.x = acc[mt][nt][2]*inv + x2.x;
            o2.y = acc[mt][nt][3]*inv + x2.y;
            *reinterpret_cast<float2*>(x1o + b2 + col) = o2;
        }
    }
}

// ---------------- launch ----------------
extern "C" void kernel_launch(void* const* d_in, const int* in_sizes, int n_in,
                              void* d_out, int out_size)
{
    const float* A      = (const float*)d_in[0];
    const float* X      = (const float*)d_in[1];
    const float* coeffs = (const float*)d_in[2];
    const float* wA1    = (const float*)d_in[3];
    const float* wA2    = (const float*)d_in[4];
    const float* w11    = (const float*)d_in[5];
    const float* w12    = (const float*)d_in[6];
    const float* w13    = (const float*)d_in[7];
    const float* w14    = (const float*)d_in[8];
    const float* w15    = (const float*)d_in[9];
    const float* w16    = (const float*)d_in[10];
    const float* w21    = (const float*)d_in[11];
    const float* w22    = (const float*)d_in[12];
    const float* w23    = (const float*)d_in[13];
    const float* w24    = (const float*)d_in[14];
    const float* w25    = (const float*)d_in[15];
    const float* w26    = (const float*)d_in[16];

    float* out = (float*)d_out;
    float* x1o = out + OUT_OFF;

    const int NODE_SMEM = (128*DD + 2*64*68) * (int)sizeof(float);  // 67584
    cudaFuncSetAttribute(k_node, cudaFuncAttributeMaxDynamicSharedMemorySize, NODE_SMEM);
    const int GEMM_SMEM = 2 * STG_F * (int)sizeof(float);           // 139264
    cudaFuncSetAttribute(k_gemm, cudaFuncAttributeMaxDynamicSharedMemorySize, GEMM_SMEM);

    k_row_stats  <<<2048, 256>>>(A, X, coeffs, wA1);
    k_batch_stats<<<16,   256>>>(X, coeffs, wA2, w12, w15, w16, w22, w25, w26);
    k_node       <<<dim3(8,16), 256, NODE_SMEM>>>(X, w11, w13, w14, w21, w23, w24, x1o);
    k_gemm       <<<dim3(8,16), 256, GEMM_SMEM>>>(A, coeffs, out, x1o);
}

// round 10
// speedup vs baseline: 1.3681x; 1.0123x over previous
#include <cuda_runtime.h>
#include <cuda_bf16.h>
#include <stdint.h>

#define NB 16
#define NN 1024
#define DD 64
#define OUT_OFF ((size_t)NB * NN * NN)

// ---------------- scratch (device globals; no allocation) ----------------
__device__ float g_rowmean[NB*NN];
__device__ float g_diag[NB*NN];
__device__ float g_r[NB*NN];            // c3*rowmean + c4*diag + p1
__device__ float g_s[NB];               // c1*mean_all + c2*mean_diag + p2
__device__ float g_pg1[NB*DD];
__device__ float g_pg2[NB*DD];
__device__ float g_BhiT[(size_t)NB*DD*NN];   // tf32-hi of X2_t^T: [b][e][k]
__device__ float g_BloT[(size_t)NB*DD*NN];   // tf32-lo residual
__device__ float g_part0[(size_t)NB*NN*DD];  // split-K partial (kv=0)
__device__ float g_part1[(size_t)NB*NN*DD];  // split-K partial (kv=1)

// ---------------- packed fp32x2 helpers (k_node) ----------------
__device__ __forceinline__ void fma2(unsigned long long &d,
                                     unsigned long long a,
                                     unsigned long long b) {
    asm("fma.rn.f32x2 %0, %1, %2, %0;" : "+l"(d) : "l"(a), "l"(b));
}
__device__ __forceinline__ float psum(unsigned long long v) {
    return __uint_as_float((unsigned)v) + __uint_as_float((unsigned)(v >> 32));
}

// ---------------- tf32 split ----------------
__device__ __forceinline__ void tf32pair(float v, uint32_t &h, uint32_t &l) {
    asm("cvt.rna.tf32.f32 %0, %1;" : "=r"(h) : "f"(v));
    float rmd = v - __uint_as_float(h);
    asm("cvt.rna.tf32.f32 %0, %1;" : "=r"(l) : "f"(rmd));
}
__device__ __forceinline__ void tf32split(float v, float &h, float &l) {
    uint32_t hb, lb;
    tf32pair(v, hb, lb);
    h = __uint_as_float(hb);
    l = __uint_as_float(lb);
}

// ---------------- m16n8k8 tf32 mma (HMMA, baseline PTX) ----------------
__device__ __forceinline__ void mma8(float* c, const uint32_t* a,
                                     uint32_t b0, uint32_t b1) {
    asm("mma.sync.aligned.m16n8k8.row.col.f32.tf32.tf32.f32 "
        "{%0,%1,%2,%3}, {%4,%5,%6,%7}, {%8,%9}, {%0,%1,%2,%3};"
        : "+f"(c[0]), "+f"(c[1]), "+f"(c[2]), "+f"(c[3])
        : "r"(a[0]), "r"(a[1]), "r"(a[2]), "r"(a[3]), "r"(b0), "r"(b1));
}

// ---------------- kernel 1: per-row stats (rowmean, diag, r) -------------
__global__ __launch_bounds__(256) void k_row_stats(
    const float* __restrict__ A, const float* __restrict__ X,
    const float* __restrict__ coeffs, const float* __restrict__ wA1)
{
    int gw = blockIdx.x * 8 + (threadIdx.x >> 5);   // global row 0..16383
    int lane = threadIdx.x & 31;
    const float4* arow = reinterpret_cast<const float4*>(A) + (size_t)gw * (NN/4);
    float s = 0.f;
#pragma unroll
    for (int w = 0; w < 8; ++w) {
        float4 v = arow[lane + (w << 5)];
        s += (v.x + v.y) + (v.z + v.w);
    }
    const float* xrow = X + (size_t)gw * DD;
    float p = xrow[lane] * wA1[lane] + xrow[lane+32] * wA1[lane+32];
#pragma unroll
    for (int o = 16; o; o >>= 1) {
        s += __shfl_xor_sync(0xffffffffu, s, o);
        p += __shfl_xor_sync(0xffffffffu, p, o);
    }
    if (lane == 0) {
        int i = gw & (NN-1);
        float d = A[(size_t)gw*NN + i];
        float rm = s * (1.f/NN);
        g_rowmean[gw] = rm;
        g_diag[gw]    = d;
        g_r[gw]       = coeffs[3]*rm + coeffs[4]*d + p;
    }
}

// ---------------- kernel 2: per-batch stats (s, pg1, pg2) ----------------
__global__ __launch_bounds__(256) void k_batch_stats(
    const float* __restrict__ X, const float* __restrict__ coeffs,
    const float* __restrict__ wA2,
    const float* __restrict__ w12, const float* __restrict__ w15, const float* __restrict__ w16,
    const float* __restrict__ w22, const float* __restrict__ w25, const float* __restrict__ w26)
{
    int b = blockIdx.x, t = threadIdx.x;
    __shared__ float red[256];
    __shared__ float sm_meanX[DD];
    __shared__ float sm_mall, sm_mdiag;

    float v1 = 0.f, v2 = 0.f;
    for (int i = t; i < NN; i += 256) { v1 += g_rowmean[b*NN+i]; v2 += g_diag[b*NN+i]; }
    red[t] = v1; __syncthreads();
    for (int o = 128; o > 0; o >>= 1) { if (t < o) red[t] += red[t+o]; __syncthreads(); }
    if (t == 0) sm_mall = red[0]*(1.f/NN);
    __syncthreads();
    red[t] = v2; __syncthreads();
    for (int o = 128; o > 0; o >>= 1) { if (t < o) red[t] += red[t+o]; __syncthreads(); }
    if (t == 0) sm_mdiag = red[0]*(1.f/NN);
    __syncthreads();

    int d = t & 63, g = t >> 6;
    float xs = 0.f;
    for (int j = g; j < NN; j += 4) xs += X[((size_t)b*NN + j)*DD + d];
    red[t] = xs; __syncthreads();
    if (g == 0) sm_meanX[d] = (red[d] + red[d+64] + red[d+128] + red[d+192]) * (1.f/NN);
    __syncthreads();

    float mall = sm_mall, mdiag = sm_mdiag;
    if (t == 0) {
        float p2 = 0.f;
        for (int k = 0; k < DD; ++k) p2 += sm_meanX[k]*wA2[k];
        g_s[b] = coeffs[1]*mall + coeffs[2]*mdiag + p2;
    } else if (t >= 64 && t < 128) {
        int e = t - 64;
        float a = 0.f;
        for (int k = 0; k < DD; ++k) a += sm_meanX[k]*w12[e*DD+k];
        g_pg1[b*DD+e] = a + mdiag*w15[e] + mall*w16[e];
    } else if (t >= 128 && t < 192) {
        int e = t - 128;
        float a = 0.f;
        for (int k = 0; k < DD; ++k) a += sm_meanX[k]*w22[e*DD+k];
        g_pg2[b*DD+e] = a + mdiag*w25[e] + mall*w26[e];
    }
}

// ---------------- kernel 3: node transforms X1_t, X2_t^T (hi/lo) ---------
// dynamic smem: Xs[128*64] | W1[64*68] | W2[64*68]  (67584 B)
__global__ __launch_bounds__(256) void k_node(
    const float* __restrict__ X,
    const float* __restrict__ w11, const float* __restrict__ w13, const float* __restrict__ w14,
    const float* __restrict__ w21, const float* __restrict__ w23, const float* __restrict__ w24,
    float* __restrict__ x1o)
{
    extern __shared__ __align__(16) float sm[];
    float* Xs = sm;               // [128][64]
    float* W1 = sm + 128*DD;      // [64][68]
    float* W2 = W1 + 64*68;       // [64][68]

    const int b = blockIdx.y;
    const int it0 = blockIdx.x << 7;    // 128 rows per block
    const int tid = threadIdx.x;
    const int c4 = tid & 15, r0 = tid >> 4;   // r0 0..15
    const int ci = c4 << 2;

    const float* Xb = X + ((size_t)b*NN + it0)*DD;
#pragma unroll
    for (int t = 0; t < 8; ++t) {
        int row = r0 + (t << 4);
        *reinterpret_cast<float4*>(Xs + row*DD + ci) =
            *reinterpret_cast<const float4*>(Xb + (size_t)row*DD + ci);
    }
#pragma unroll
    for (int t = 0; t < 4; ++t) {
        int e = r0 + (t << 4);
        *reinterpret_cast<float4*>(W1 + e*68 + ci) = *reinterpret_cast<const float4*>(w11 + e*DD + ci);
        *reinterpret_cast<float4*>(W2 + e*68 + ci) = *reinterpret_cast<const float4*>(w21 + e*DD + ci);
    }
    __syncthreads();

    const int tx = tid & 15, ty = tid >> 4;
    const int e0 = tx << 2, i0 = ty << 3;   // i0 0..120

    float rmv[8], dgv[8];
#pragma unroll
    for (int r = 0; r < 8; ++r) {
        int row = b*NN + it0 + i0 + r;
        rmv[r] = g_rowmean[row];
        dgv[r] = g_diag[row];
    }

    unsigned long long acc[8][4];

    // ---- pass 1: X1_t -> x1o ----
#pragma unroll
    for (int r = 0; r < 8; ++r)
#pragma unroll
        for (int q = 0; q < 4; ++q) acc[r][q] = 0ull;
#pragma unroll 2
    for (int d = 0; d < DD; d += 4) {
        ulonglong2 a[8];
#pragma unroll
        for (int r = 0; r < 8; ++r)
            a[r] = *reinterpret_cast<const ulonglong2*>(Xs + (i0+r)*DD + d);
#pragma unroll
        for (int q = 0; q < 4; ++q) {
            ulonglong2 bv = *reinterpret_cast<const ulonglong2*>(W1 + (e0+q)*68 + d);
#pragma unroll
            for (int r = 0; r < 8; ++r) { fma2(acc[r][q], a[r].x, bv.x); fma2(acc[r][q], a[r].y, bv.y); }
        }
    }
    {
        float4 wc = *reinterpret_cast<const float4*>(w13 + e0);
        float4 wd = *reinterpret_cast<const float4*>(w14 + e0);
        float4 pg = *reinterpret_cast<const float4*>(g_pg1 + b*DD + e0);
#pragma unroll
        for (int r = 0; r < 8; ++r) {
            float4 o;
            o.x = psum(acc[r][0]) + rmv[r]*wc.x + dgv[r]*wd.x + pg.x;
            o.y = psum(acc[r][1]) + rmv[r]*wc.y + dgv[r]*wd.y + pg.y;
            o.z = psum(acc[r][2]) + rmv[r]*wc.z + dgv[r]*wd.z + pg.z;
            o.w = psum(acc[r][3]) + rmv[r]*wc.w + dgv[r]*wd.w + pg.w;
            *reinterpret_cast<float4*>(x1o + ((size_t)b*NN + it0 + i0 + r)*DD + e0) = o;
        }
    }

    // ---- pass 2: X2_t -> registers, then SMEM-bounce transpose ----
#pragma unroll
    for (int r = 0; r < 8; ++r)
#pragma unroll
        for (int q = 0; q < 4; ++q) acc[r][q] = 0ull;
#pragma unroll 2
    for (int d = 0; d < DD; d += 4) {
        ulonglong2 a[8];
#pragma unroll
        for (int r = 0; r < 8; ++r)
            a[r] = *reinterpret_cast<const ulonglong2*>(Xs + (i0+r)*DD + d);
#pragma unroll
        for (int q = 0; q < 4; ++q) {
            ulonglong2 bv = *reinterpret_cast<const ulonglong2*>(W2 + (e0+q)*68 + d);
#pragma unroll
            for (int r = 0; r < 8; ++r) { fma2(acc[r][q], a[r].x, bv.x); fma2(acc[r][q], a[r].y, bv.y); }
        }
    }
    float4 o2v[8];
    {
        float4 wc = *reinterpret_cast<const float4*>(w23 + e0);
        float4 wd = *reinterpret_cast<const float4*>(w24 + e0);
        float4 pg = *reinterpret_cast<const float4*>(g_pg2 + b*DD + e0);
#pragma unroll
        for (int r = 0; r < 8; ++r) {
            o2v[r].x = psum(acc[r][0]) + rmv[r]*wc.x + dgv[r]*wd.x + pg.x;
            o2v[r].y = psum(acc[r][1]) + rmv[r]*wc.y + dgv[r]*wd.y + pg.y;
            o2v[r].z = psum(acc[r][2]) + rmv[r]*wc.z + dgv[r]*wd.z + pg.z;
            o2v[r].w = psum(acc[r][3]) + rmv[r]*wc.w + dgv[r]*wd.w + pg.w;
        }
    }
    __syncthreads();   // all reads of Xs done -> reuse as transpose buffer
#pragma unroll
    for (int r = 0; r < 8; ++r)
        *reinterpret_cast<float4*>(Xs + (i0+r)*DD + e0) = o2v[r];
    __syncthreads();

    // transposed hi/lo write: g_BhiT/g_BloT [b][e][j]
    const int e = tid & 63, rc = tid >> 6;   // rc 0..3
#pragma unroll
    for (int rr = 0; rr < 8; ++rr) {
        int rowl = (rc << 5) + (rr << 2);
        float4 h, l;
        tf32split(Xs[(rowl+0)*DD + e], h.x, l.x);
        tf32split(Xs[(rowl+1)*DD + e], h.y, l.y);
        tf32split(Xs[(rowl+2)*DD + e], h.z, l.z);
        tf32split(Xs[(rowl+3)*DD + e], h.w, l.w);
        size_t off = ((size_t)b*DD + e)*NN + it0 + rowl;
        *reinterpret_cast<float4*>(g_BhiT + off) = h;
        *reinterpret_cast<float4*>(g_BloT + off) = l;
    }
}

// ---------------- kernel 4: HMMA tf32 GEMM (3xTF32, split-K=2) -----------
// 256 threads, 128x64 tile, KC=32, double-buffered 72KB smem -> 2 CTAs/SM.
// gridDim.z = split-K index; each block owns K=512 and writes its own
// k-range of A_t plus a partial-sum buffer (no atomics; k_fix reduces).
#define KC 32
#define STG_F (128*36 + 2*64*36)   // 9216 floats per stage (36 KB)
__global__ __launch_bounds__(256, 2) void k_gemm(
    const float* __restrict__ A, const float* __restrict__ coeffs,
    float* __restrict__ At)
{
    extern __shared__ __align__(16) float sm[];
    const int tid = threadIdx.x;
    const int wid = tid >> 5, lane = tid & 31;
    const int b = blockIdx.y, it0 = blockIdx.x << 7;
    const int kv = blockIdx.z;
    const int kbase = kv << 9;          // 0 or 512

    // loader coords (KC=32)
    const int rb = tid >> 3;            // 0..31 (A rows rb+32i)
    const int ci = (tid & 7) << 2;      // 0..28
    const int eb = tid >> 2;            // 0..63 (B row)
    const int kq = (tid & 3) << 3;      // 0,8,16,24

    const float c0 = coeffs[0];
    const float sbv = g_s[b];
    float rloc[4];
#pragma unroll
    for (int i = 0; i < 4; ++i) rloc[i] = sbv + g_r[b*NN + it0 + rb + (i << 5)];

    const float* Ab = A  + ((size_t)b*NN + it0)*NN;
    float*       Ob = At + ((size_t)b*NN + it0)*NN;
    const float* Bh = g_BhiT + (size_t)b*DD*NN;
    const float* Bl = g_BloT + (size_t)b*DD*NN;
    float*       Pb = (kv == 0 ? g_part0 : g_part1) + ((size_t)b*NN + it0)*DD;

    float acc[2][4][4];
#pragma unroll
    for (int mt = 0; mt < 2; ++mt)
#pragma unroll
        for (int nt = 0; nt < 4; ++nt)
#pragma unroll
            for (int q = 0; q < 4; ++q) acc[mt][nt][q] = 0.f;

    float4 Ar[4], Bhr[2], Blr[2], rjv;
    auto fetch = [&](int s) {
        const int k0 = kbase + (s << 5);
        rjv = *reinterpret_cast<const float4*>(g_r + b*NN + k0 + ci);
#pragma unroll
        for (int i = 0; i < 4; ++i)
            Ar[i] = *reinterpret_cast<const float4*>(Ab + (size_t)(rb + (i << 5))*NN + k0 + ci);
#pragma unroll
        for (int q = 0; q < 2; ++q) {
            Bhr[q] = *reinterpret_cast<const float4*>(Bh + (size_t)eb*NN + k0 + kq + (q << 2));
            Blr[q] = *reinterpret_cast<const float4*>(Bl + (size_t)eb*NN + k0 + kq + (q << 2));
        }
    };
    auto fill = [&](int s, int buf) {
        const int k0 = kbase + (s << 5);
        float* As  = sm + buf * STG_F;
        float* Bsh = As + 128*36;
        float* Bsl = Bsh + 64*36;
#pragma unroll
        for (int i = 0; i < 4; ++i) {
            int row = rb + (i << 5);
            float4 atv;
            atv.x = fmaf(c0, Ar[i].x, rloc[i] + rjv.x);
            atv.y = fmaf(c0, Ar[i].y, rloc[i] + rjv.y);
            atv.z = fmaf(c0, Ar[i].z, rloc[i] + rjv.z);
            atv.w = fmaf(c0, Ar[i].w, rloc[i] + rjv.w);
            *reinterpret_cast<float4*>(Ob + (size_t)row*NN + k0 + ci) = atv;   // A_t out
            *reinterpret_cast<float4*>(As + row*36 + ci) = atv;
        }
#pragma unroll
        for (int q = 0; q < 2; ++q) {
            *reinterpret_cast<float4*>(Bsh + eb*36 + kq + (q << 2)) = Bhr[q];
            *reinterpret_cast<float4*>(Bsl + eb*36 + kq + (q << 2)) = Blr[q];
        }
    };

    const int g = lane >> 2, t = lane & 3;
    const int m0 = (wid & 3) << 5;       // 4 m-groups of 32 rows
    const int e0 = (wid >> 2) << 5;      // 2 e-groups of 32 cols

    fetch(0);
    fill(0, 0);
    __syncthreads();

    for (int s = 0; s < 16; ++s) {
        if (s < 15) fetch(s + 1);        // LDG in flight behind MMAs
        const float* As  = sm + (s & 1) * STG_F;
        const float* Bsh = As + 128*36;
        const float* Bsl = Bsh + 64*36;
#pragma unroll
        for (int ks = 0; ks < 4; ++ks) {
            const int kk = ks << 3;
            uint32_t ah[2][4], al[2][4];
#pragma unroll
            for (int mt = 0; mt < 2; ++mt) {
                const int rowb = m0 + (mt << 4);
                tf32pair(As[(rowb+g  )*36 + kk + t    ], ah[mt][0], al[mt][0]);
                tf32pair(As[(rowb+g+8)*36 + kk + t    ], ah[mt][1], al[mt][1]);
                tf32pair(As[(rowb+g  )*36 + kk + t + 4], ah[mt][2], al[mt][2]);
                tf32pair(As[(rowb+g+8)*36 + kk + t + 4], ah[mt][3], al[mt][3]);
            }
            uint32_t bh[4][2], bl[4][2];
#pragma unroll
            for (int nt = 0; nt < 4; ++nt) {
                const int er = (e0 + (nt << 3) + g)*36 + kk + t;
                bh[nt][0] = __float_as_uint(Bsh[er    ]);
                bh[nt][1] = __float_as_uint(Bsh[er + 4]);
                bl[nt][0] = __float_as_uint(Bsl[er    ]);
                bl[nt][1] = __float_as_uint(Bsl[er + 4]);
            }
#pragma unroll
            for (int mt = 0; mt < 2; ++mt)
#pragma unroll
                for (int nt = 0; nt < 4; ++nt)
                    mma8(acc[mt][nt], ah[mt], bh[nt][0], bh[nt][1]);
#pragma unroll
            for (int mt = 0; mt < 2; ++mt)
#pragma unroll
                for (int nt = 0; nt < 4; ++nt)
                    mma8(acc[mt][nt], ah[mt], bl[nt][0], bl[nt][1]);
#pragma unroll
            for (int mt = 0; mt < 2; ++mt)
#pragma unroll
                for (int nt = 0; nt < 4; ++nt)
                    mma8(acc[mt][nt], al[mt], bh[nt][0], bh[nt][1]);
        }
        if (s < 15) {
            fill(s + 1, (s + 1) & 1);    // writes the other buffer
            __syncthreads();
        }
    }

    // ---- epilogue: store raw partial sums ----
#pragma unroll
    for (int mt = 0; mt < 2; ++mt) {
        const int row1 = m0 + (mt << 4) + g;
        const size_t b1 = (size_t)row1*DD;
        const size_t b2 = b1 + 8*DD;
#pragma unroll
        for (int nt = 0; nt < 4; ++nt) {
            const int col = e0 + (nt << 3) + (t << 1);
            float2 o1; o1.x = acc[mt][nt][0]; o1.y = acc[mt][nt][1];
            *reinterpret_cast<float2*>(Pb + b1 + col) = o1;
            float2 o2; o2.x = acc[mt][nt][2]; o2.y = acc[mt][nt][3];
            *reinterpret_cast<float2*>(Pb + b2 + col) = o2;
        }
    }
}

// ---------------- kernel 5: fold split-K partials into X1_t --------------
__global__ __launch_bounds__(256) void k_fix(float* __restrict__ x1o) {
    const size_t i = ((size_t)blockIdx.x * 256 + threadIdx.x) << 2;
    const float inv = 1.0f / 1024.0f;
    float4 p0 = *reinterpret_cast<const float4*>(g_part0 + i);
    float4 p1 = *reinterpret_cast<const float4*>(g_part1 + i);
    float4 x  = *reinterpret_cast<const float4*>(x1o + i);
    x.x += (p0.x + p1.x) * inv;
    x.y += (p0.y + p1.y) * inv;
    x.z += (p0.z + p1.z) * inv;
    x.w += (p0.w + p1.w) * inv;
    *reinterpret_cast<float4*>(x1o + i) = x;
}

// ---------------- launch ----------------
extern "C" void kernel_launch(void* const* d_in, const int* in_sizes, int n_in,
                              void* d_out, int out_size)
{
    const float* A      = (const float*)d_in[0];
    const float* X      = (const float*)d_in[1];
    const float* coeffs = (const float*)d_in[2];
    const float* wA1    = (const float*)d_in[3];
    const float* wA2    = (const float*)d_in[4];
    const float* w11    = (const float*)d_in[5];
    const float* w12    = (const float*)d_in[6];
    const float* w13    = (const float*)d_in[7];
    const float* w14    = (const float*)d_in[8];
    const float* w15    = (const float*)d_in[9];
    const float* w16    = (const float*)d_in[10];
    const float* w21    = (const float*)d_in[11];
    const float* w22    = (const float*)d_in[12];
    const float* w23    = (const float*)d_in[13];
    const float* w24    = (const float*)d_in[14];
    const float* w25    = (const float*)d_in[15];
    const float* w26    = (const float*)d_in[16];

    float* out = (float*)d_out;
    float* x1o = out + OUT_OFF;

    const int NODE_SMEM = (128*DD + 2*64*68) * (int)sizeof(float);  // 67584
    cudaFuncSetAttribute(k_node, cudaFuncAttributeMaxDynamicSharedMemorySize, NODE_SMEM);
    const int GEMM_SMEM = 2 * STG_F * (int)sizeof(float);           // 73728
    cudaFuncSetAttribute(k_gemm, cudaFuncAttributeMaxDynamicSharedMemorySize, GEMM_SMEM);

    k_row_stats  <<<2048, 256>>>(A, X, coeffs, wA1);
    k_batch_stats<<<16,   256>>>(X, coeffs, wA2, w12, w15, w16, w22, w25, w26);
    k_node       <<<dim3(8,16), 256, NODE_SMEM>>>(X, w11, w13, w14, w21, w23, w24, x1o);
    k_gemm       <<<dim3(8,16,2), 256, GEMM_SMEM>>>(A, coeffs, out);
    k_fix        <<<(NB*NN*DD)/(256*4), 256>>>(x1o);
}

// round 11
// speedup vs baseline: 1.6527x; 1.2080x over previous
#include <cuda_runtime.h>
#include <cuda_bf16.h>
#include <stdint.h>

#define NB 16
#define NN 1024
#define DD 64
#define OUT_OFF ((size_t)NB * NN * NN)

// ---------------- scratch (device globals; no allocation) ----------------
__device__ float g_rowmean[NB*NN];
__device__ float g_diag[NB*NN];
__device__ float g_r[NB*NN];            // c3*rowmean + c4*diag + p1
__device__ float g_s[NB];               // c1*mean_all + c2*mean_diag + p2
__device__ float g_pg1[NB*DD];
__device__ float g_pg2[NB*DD];
__device__ uint32_t g_Bhi[(size_t)NB*DD*NN/2];  // bf16x2-packed hi of X2_t^T [b][e][k/2]
__device__ uint32_t g_Blo[(size_t)NB*DD*NN/2];  // bf16x2-packed lo residual
__device__ float g_part0[(size_t)NB*NN*DD];     // split-K partial (kv=0)
__device__ float g_part1[(size_t)NB*NN*DD];     // split-K partial (kv=1)

// ---------------- packed fp32x2 helpers (k_node) ----------------
__device__ __forceinline__ void fma2(unsigned long long &d,
                                     unsigned long long a,
                                     unsigned long long b) {
    asm("fma.rn.f32x2 %0, %1, %2, %0;" : "+l"(d) : "l"(a), "l"(b));
}
__device__ __forceinline__ float psum(unsigned long long v) {
    return __uint_as_float((unsigned)v) + __uint_as_float((unsigned)(v >> 32));
}

// ---------------- bf16 split helpers ----------------
// result = [hi16(a) | hi16(b)<<16]  (bf16x2 pack: a -> low half = even k)
__device__ __forceinline__ uint32_t prmt7632(uint32_t a, uint32_t b) {
    uint32_t d;
    asm("prmt.b32 %0, %1, %2, 0x7632;" : "=r"(d) : "r"(a), "r"(b));
    return d;
}

// ---------------- m16n8k16 bf16 mma (HMMA, baseline PTX) ----------------
__device__ __forceinline__ void mma16(float* c, const uint32_t* a,
                                      uint32_t b0, uint32_t b1) {
    asm("mma.sync.aligned.m16n8k16.row.col.f32.bf16.bf16.f32 "
        "{%0,%1,%2,%3}, {%4,%5,%6,%7}, {%8,%9}, {%0,%1,%2,%3};"
        : "+f"(c[0]), "+f"(c[1]), "+f"(c[2]), "+f"(c[3])
        : "r"(a[0]), "r"(a[1]), "r"(a[2]), "r"(a[3]), "r"(b0), "r"(b1));
}

// ---------------- kernel 1: per-row stats (rowmean, diag, r) -------------
__global__ __launch_bounds__(256) void k_row_stats(
    const float* __restrict__ A, const float* __restrict__ X,
    const float* __restrict__ coeffs, const float* __restrict__ wA1)
{
    int gw = blockIdx.x * 8 + (threadIdx.x >> 5);   // global row 0..16383
    int lane = threadIdx.x & 31;
    const float4* arow = reinterpret_cast<const float4*>(A) + (size_t)gw * (NN/4);
    float s = 0.f;
#pragma unroll
    for (int w = 0; w < 8; ++w) {
        float4 v = arow[lane + (w << 5)];
        s += (v.x + v.y) + (v.z + v.w);
    }
    const float* xrow = X + (size_t)gw * DD;
    float p = xrow[lane] * wA1[lane] + xrow[lane+32] * wA1[lane+32];
#pragma unroll
    for (int o = 16; o; o >>= 1) {
        s += __shfl_xor_sync(0xffffffffu, s, o);
        p += __shfl_xor_sync(0xffffffffu, p, o);
    }
    if (lane == 0) {
        int i = gw & (NN-1);
        float d = A[(size_t)gw*NN + i];
        float rm = s * (1.f/NN);
        g_rowmean[gw] = rm;
        g_diag[gw]    = d;
        g_r[gw]       = coeffs[3]*rm + coeffs[4]*d + p;
    }
}

// ---------------- kernel 2: per-batch stats (s, pg1, pg2) ----------------
__global__ __launch_bounds__(256) void k_batch_stats(
    const float* __restrict__ X, const float* __restrict__ coeffs,
    const float* __restrict__ wA2,
    const float* __restrict__ w12, const float* __restrict__ w15, const float* __restrict__ w16,
    const float* __restrict__ w22, const float* __restrict__ w25, const float* __restrict__ w26)
{
    int b = blockIdx.x, t = threadIdx.x;
    __shared__ float red[256];
    __shared__ float sm_meanX[DD];
    __shared__ float sm_mall, sm_mdiag;

    float v1 = 0.f, v2 = 0.f;
    for (int i = t; i < NN; i += 256) { v1 += g_rowmean[b*NN+i]; v2 += g_diag[b*NN+i]; }
    red[t] = v1; __syncthreads();
    for (int o = 128; o > 0; o >>= 1) { if (t < o) red[t] += red[t+o]; __syncthreads(); }
    if (t == 0) sm_mall = red[0]*(1.f/NN);
    __syncthreads();
    red[t] = v2; __syncthreads();
    for (int o = 128; o > 0; o >>= 1) { if (t < o) red[t] += red[t+o]; __syncthreads(); }
    if (t == 0) sm_mdiag = red[0]*(1.f/NN);
    __syncthreads();

    int d = t & 63, g = t >> 6;
    float xs = 0.f;
    for (int j = g; j < NN; j += 4) xs += X[((size_t)b*NN + j)*DD + d];
    red[t] = xs; __syncthreads();
    if (g == 0) sm_meanX[d] = (red[d] + red[d+64] + red[d+128] + red[d+192]) * (1.f/NN);
    __syncthreads();

    float mall = sm_mall, mdiag = sm_mdiag;
    if (t == 0) {
        float p2 = 0.f;
        for (int k = 0; k < DD; ++k) p2 += sm_meanX[k]*wA2[k];
        g_s[b] = coeffs[1]*mall + coeffs[2]*mdiag + p2;
    } else if (t >= 64 && t < 128) {
        int e = t - 64;
        float a = 0.f;
        for (int k = 0; k < DD; ++k) a += sm_meanX[k]*w12[e*DD+k];
        g_pg1[b*DD+e] = a + mdiag*w15[e] + mall*w16[e];
    } else if (t >= 128 && t < 192) {
        int e = t - 128;
        float a = 0.f;
        for (int k = 0; k < DD; ++k) a += sm_meanX[k]*w22[e*DD+k];
        g_pg2[b*DD+e] = a + mdiag*w25[e] + mall*w26[e];
    }
}

// ---------------- kernel 3: node transforms X1_t, X2_t^T (bf16 hi/lo) ----
// dynamic smem: Xs[128*64] | W1[64*68] | W2[64*68]  (67584 B)
__global__ __launch_bounds__(256) void k_node(
    const float* __restrict__ X,
    const float* __restrict__ w11, const float* __restrict__ w13, const float* __restrict__ w14,
    const float* __restrict__ w21, const float* __restrict__ w23, const float* __restrict__ w24,
    float* __restrict__ x1o)
{
    extern __shared__ __align__(16) float sm[];
    float* Xs = sm;               // [128][64]
    float* W1 = sm + 128*DD;      // [64][68]
    float* W2 = W1 + 64*68;       // [64][68]

    const int b = blockIdx.y;
    const int it0 = blockIdx.x << 7;    // 128 rows per block
    const int tid = threadIdx.x;
    const int c4 = tid & 15, r0 = tid >> 4;   // r0 0..15
    const int ci = c4 << 2;

    const float* Xb = X + ((size_t)b*NN + it0)*DD;
#pragma unroll
    for (int t = 0; t < 8; ++t) {
        int row = r0 + (t << 4);
        *reinterpret_cast<float4*>(Xs + row*DD + ci) =
            *reinterpret_cast<const float4*>(Xb + (size_t)row*DD + ci);
    }
#pragma unroll
    for (int t = 0; t < 4; ++t) {
        int e = r0 + (t << 4);
        *reinterpret_cast<float4*>(W1 + e*68 + ci) = *reinterpret_cast<const float4*>(w11 + e*DD + ci);
        *reinterpret_cast<float4*>(W2 + e*68 + ci) = *reinterpret_cast<const float4*>(w21 + e*DD + ci);
    }
    __syncthreads();

    const int tx = tid & 15, ty = tid >> 4;
    const int e0 = tx << 2, i0 = ty << 3;   // i0 0..120

    float rmv[8], dgv[8];
#pragma unroll
    for (int r = 0; r < 8; ++r) {
        int row = b*NN + it0 + i0 + r;
        rmv[r] = g_rowmean[row];
        dgv[r] = g_diag[row];
    }

    unsigned long long acc[8][4];

    // ---- pass 1: X1_t -> x1o ----
#pragma unroll
    for (int r = 0; r < 8; ++r)
#pragma unroll
        for (int q = 0; q < 4; ++q) acc[r][q] = 0ull;
#pragma unroll 2
    for (int d = 0; d < DD; d += 4) {
        ulonglong2 a[8];
#pragma unroll
        for (int r = 0; r < 8; ++r)
            a[r] = *reinterpret_cast<const ulonglong2*>(Xs + (i0+r)*DD + d);
#pragma unroll
        for (int q = 0; q < 4; ++q) {
            ulonglong2 bv = *reinterpret_cast<const ulonglong2*>(W1 + (e0+q)*68 + d);
#pragma unroll
            for (int r = 0; r < 8; ++r) { fma2(acc[r][q], a[r].x, bv.x); fma2(acc[r][q], a[r].y, bv.y); }
        }
    }
    {
        float4 wc = *reinterpret_cast<const float4*>(w13 + e0);
        float4 wd = *reinterpret_cast<const float4*>(w14 + e0);
        float4 pg = *reinterpret_cast<const float4*>(g_pg1 + b*DD + e0);
#pragma unroll
        for (int r = 0; r < 8; ++r) {
            float4 o;
            o.x = psum(acc[r][0]) + rmv[r]*wc.x + dgv[r]*wd.x + pg.x;
            o.y = psum(acc[r][1]) + rmv[r]*wc.y + dgv[r]*wd.y + pg.y;
            o.z = psum(acc[r][2]) + rmv[r]*wc.z + dgv[r]*wd.z + pg.z;
            o.w = psum(acc[r][3]) + rmv[r]*wc.w + dgv[r]*wd.w + pg.w;
            *reinterpret_cast<float4*>(x1o + ((size_t)b*NN + it0 + i0 + r)*DD + e0) = o;
        }
    }

    // ---- pass 2: X2_t -> registers, then SMEM-bounce transpose ----
#pragma unroll
    for (int r = 0; r < 8; ++r)
#pragma unroll
        for (int q = 0; q < 4; ++q) acc[r][q] = 0ull;
#pragma unroll 2
    for (int d = 0; d < DD; d += 4) {
        ulonglong2 a[8];
#pragma unroll
        for (int r = 0; r < 8; ++r)
            a[r] = *reinterpret_cast<const ulonglong2*>(Xs + (i0+r)*DD + d);
#pragma unroll
        for (int q = 0; q < 4; ++q) {
            ulonglong2 bv = *reinterpret_cast<const ulonglong2*>(W2 + (e0+q)*68 + d);
#pragma unroll
            for (int r = 0; r < 8; ++r) { fma2(acc[r][q], a[r].x, bv.x); fma2(acc[r][q], a[r].y, bv.y); }
        }
    }
    float4 o2v[8];
    {
        float4 wc = *reinterpret_cast<const float4*>(w23 + e0);
        float4 wd = *reinterpret_cast<const float4*>(w24 + e0);
        float4 pg = *reinterpret_cast<const float4*>(g_pg2 + b*DD + e0);
#pragma unroll
        for (int r = 0; r < 8; ++r) {
            o2v[r].x = psum(acc[r][0]) + rmv[r]*wc.x + dgv[r]*wd.x + pg.x;
            o2v[r].y = psum(acc[r][1]) + rmv[r]*wc.y + dgv[r]*wd.y + pg.y;
            o2v[r].z = psum(acc[r][2]) + rmv[r]*wc.z + dgv[r]*wd.z + pg.z;
            o2v[r].w = psum(acc[r][3]) + rmv[r]*wc.w + dgv[r]*wd.w + pg.w;
        }
    }
    __syncthreads();   // all reads of Xs done -> reuse as transpose buffer
#pragma unroll
    for (int r = 0; r < 8; ++r)
        *reinterpret_cast<float4*>(Xs + (i0+r)*DD + e0) = o2v[r];
    __syncthreads();

    // transposed bf16 hi/lo packed write: g_Bhi/g_Blo [b][e][k/2]
    const int e = tid & 63, rc = tid >> 6;   // rc 0..3
#pragma unroll
    for (int rr = 0; rr < 8; ++rr) {
        int rowl = (rc << 5) + (rr << 2);
        float v0 = Xs[(rowl+0)*DD + e], v1 = Xs[(rowl+1)*DD + e];
        float v2 = Xs[(rowl+2)*DD + e], v3 = Xs[(rowl+3)*DD + e];
        uint32_t b0 = __float_as_uint(v0), b1 = __float_as_uint(v1);
        uint32_t b2 = __float_as_uint(v2), b3 = __float_as_uint(v3);
        float l0 = v0 - __uint_as_float(b0 & 0xffff0000u);
        float l1 = v1 - __uint_as_float(b1 & 0xffff0000u);
        float l2 = v2 - __uint_as_float(b2 & 0xffff0000u);
        float l3 = v3 - __uint_as_float(b3 & 0xffff0000u);
        uint2 hp, lp;
        hp.x = prmt7632(b0, b1); hp.y = prmt7632(b2, b3);
        lp.x = prmt7632(__float_as_uint(l0), __float_as_uint(l1));
        lp.y = prmt7632(__float_as_uint(l2), __float_as_uint(l3));
        size_t off = (((size_t)b*DD + e)*NN + it0 + rowl) >> 1;
        *reinterpret_cast<uint2*>(g_Bhi + off) = hp;
        *reinterpret_cast<uint2*>(g_Blo + off) = lp;
    }
}

// ---------------- kernel 4: bf16x3 HMMA GEMM (split-K=2) -----------------
// 256 threads, 128x64 tile, KC=32, double-buffered 60KB smem -> 2 CTAs/SM.
// A_t computed fp32 (exact STG) then split to packed-bf16 hi/lo in SMEM;
// B pre-split by k_node. 3 passes (hh, hl, lh) via m16n8k16.bf16.
#define STG_U (2*128*20 + 2*64*20)   // 7680 u32 per stage (30 KB)
__global__ __launch_bounds__(256, 2) void k_gemm(
    const float* __restrict__ A, const float* __restrict__ coeffs,
    float* __restrict__ At)
{
    extern __shared__ __align__(16) uint32_t smu[];
    const int tid = threadIdx.x;
    const int wid = tid >> 5, lane = tid & 31;
    const int b = blockIdx.y, it0 = blockIdx.x << 7;
    const int kv = blockIdx.z;
    const int kbase = kv << 9;          // 0 or 512

    // loader coords (KC=32)
    const int rb = tid >> 3;            // 0..31 (A rows rb+32i)
    const int ci = (tid & 7) << 2;      // 0..28 (k floats)
    const int eb = tid >> 2;            // 0..63 (B row)
    const int uc = (tid & 3) << 2;      // 0,4,8,12 (u32 cols)

    const float c0 = coeffs[0];
    const float sbv = g_s[b];
    float rloc[4];
#pragma unroll
    for (int i = 0; i < 4; ++i) rloc[i] = sbv + g_r[b*NN + it0 + rb + (i << 5)];

    const float* Ab = A  + ((size_t)b*NN + it0)*NN;
    float*       Ob = At + ((size_t)b*NN + it0)*NN;
    const uint32_t* Bhg = g_Bhi + (size_t)b*DD*(NN/2);
    const uint32_t* Blg = g_Blo + (size_t)b*DD*(NN/2);
    float*       Pb = (kv == 0 ? g_part0 : g_part1) + ((size_t)b*NN + it0)*DD;

    float acc[2][4][4];
#pragma unroll
    for (int mt = 0; mt < 2; ++mt)
#pragma unroll
        for (int nt = 0; nt < 4; ++nt)
#pragma unroll
            for (int q = 0; q < 4; ++q) acc[mt][nt][q] = 0.f;

    float4 Ar[4], rjv;
    uint4 Bh4, Bl4;
    auto fetch = [&](int s) {
        const int k0 = kbase + (s << 5);
        rjv = *reinterpret_cast<const float4*>(g_r + b*NN + k0 + ci);
#pragma unroll
        for (int i = 0; i < 4; ++i)
            Ar[i] = *reinterpret_cast<const float4*>(Ab + (size_t)(rb + (i << 5))*NN + k0 + ci);
        const int k0u = k0 >> 1;
        Bh4 = *reinterpret_cast<const uint4*>(Bhg + (size_t)eb*(NN/2) + k0u + uc);
        Bl4 = *reinterpret_cast<const uint4*>(Blg + (size_t)eb*(NN/2) + k0u + uc);
    };
    auto fill = [&](int s, int buf) {
        const int k0 = kbase + (s << 5);
        uint32_t* Ahi = smu + buf * STG_U;
        uint32_t* Alo = Ahi + 128*20;
        uint32_t* Bhi = Alo + 128*20;
        uint32_t* Blo = Bhi + 64*20;
#pragma unroll
        for (int i = 0; i < 4; ++i) {
            int row = rb + (i << 5);
            float4 atv;
            atv.x = fmaf(c0, Ar[i].x, rloc[i] + rjv.x);
            atv.y = fmaf(c0, Ar[i].y, rloc[i] + rjv.y);
            atv.z = fmaf(c0, Ar[i].z, rloc[i] + rjv.z);
            atv.w = fmaf(c0, Ar[i].w, rloc[i] + rjv.w);
            *reinterpret_cast<float4*>(Ob + (size_t)row*NN + k0 + ci) = atv;   // A_t out
            uint32_t bx = __float_as_uint(atv.x), by = __float_as_uint(atv.y);
            uint32_t bz = __float_as_uint(atv.z), bw = __float_as_uint(atv.w);
            float lx = atv.x - __uint_as_float(bx & 0xffff0000u);
            float ly = atv.y - __uint_as_float(by & 0xffff0000u);
            float lz = atv.z - __uint_as_float(bz & 0xffff0000u);
            float lw = atv.w - __uint_as_float(bw & 0xffff0000u);
            uint2 hp, lp;
            hp.x = prmt7632(bx, by); hp.y = prmt7632(bz, bw);
            lp.x = prmt7632(__float_as_uint(lx), __float_as_uint(ly));
            lp.y = prmt7632(__float_as_uint(lz), __float_as_uint(lw));
            *reinterpret_cast<uint2*>(Ahi + row*20 + (ci >> 1)) = hp;
            *reinterpret_cast<uint2*>(Alo + row*20 + (ci >> 1)) = lp;
        }
        *reinterpret_cast<uint4*>(Bhi + eb*20 + uc) = Bh4;
        *reinterpret_cast<uint4*>(Blo + eb*20 + uc) = Bl4;
    };

    const int g = lane >> 2, t = lane & 3;
    const int m0 = (wid & 3) << 5;       // 4 m-groups of 32 rows
    const int e0 = (wid >> 2) << 5;      // 2 e-groups of 32 cols

    fetch(0);
    fill(0, 0);
    __syncthreads();

    for (int s = 0; s < 16; ++s) {
        if (s < 15) fetch(s + 1);        // LDG in flight behind MMAs
        const uint32_t* Ahi = smu + (s & 1) * STG_U;
        const uint32_t* Alo = Ahi + 128*20;
        const uint32_t* Bhi = Alo + 128*20;
        const uint32_t* Blo = Bhi + 64*20;
#pragma unroll
        for (int ks = 0; ks < 2; ++ks) {
            const int kk2 = ks << 3;     // u32 offset (k16 step = 8 u32)
            uint32_t ah[2][4], al[2][4];
#pragma unroll
            for (int mt = 0; mt < 2; ++mt) {
                const int rowb = m0 + (mt << 4);
                ah[mt][0] = Ahi[(rowb+g  )*20 + kk2 + t];
                ah[mt][1] = Ahi[(rowb+g+8)*20 + kk2 + t];
                ah[mt][2] = Ahi[(rowb+g  )*20 + kk2 + 4 + t];
                ah[mt][3] = Ahi[(rowb+g+8)*20 + kk2 + 4 + t];
                al[mt][0] = Alo[(rowb+g  )*20 + kk2 + t];
                al[mt][1] = Alo[(rowb+g+8)*20 + kk2 + t];
                al[mt][2] = Alo[(rowb+g  )*20 + kk2 + 4 + t];
                al[mt][3] = Alo[(rowb+g+8)*20 + kk2 + 4 + t];
            }
            uint32_t bh[4][2], bl[4][2];
#pragma unroll
            for (int nt = 0; nt < 4; ++nt) {
                const int er = (e0 + (nt << 3) + g)*20 + kk2 + t;
                bh[nt][0] = Bhi[er]; bh[nt][1] = Bhi[er + 4];
                bl[nt][0] = Blo[er]; bl[nt][1] = Blo[er + 4];
            }
#pragma unroll
            for (int mt = 0; mt < 2; ++mt)
#pragma unroll
                for (int nt = 0; nt < 4; ++nt)
                    mma16(acc[mt][nt], ah[mt], bh[nt][0], bh[nt][1]);
#pragma unroll
            for (int mt = 0; mt < 2; ++mt)
#pragma unroll
                for (int nt = 0; nt < 4; ++nt)
                    mma16(acc[mt][nt], ah[mt], bl[nt][0], bl[nt][1]);
#pragma unroll
            for (int mt = 0; mt < 2; ++mt)
#pragma unroll
                for (int nt = 0; nt < 4; ++nt)
                    mma16(acc[mt][nt], al[mt], bh[nt][0], bh[nt][1]);
        }
        if (s < 15) {
            fill(s + 1, (s + 1) & 1);    // writes the other buffer
            __syncthreads();
        }
    }

    // ---- epilogue: store raw partial sums ----
#pragma unroll
    for (int mt = 0; mt < 2; ++mt) {
        const int row1 = m0 + (mt << 4) + g;
        const size_t b1 = (size_t)row1*DD;
        const size_t b2 = b1 + 8*DD;
#pragma unroll
        for (int nt = 0; nt < 4; ++nt) {
            const int col = e0 + (nt << 3) + (t << 1);
            float2 o1; o1.x = acc[mt][nt][0]; o1.y = acc[mt][nt][1];
            *reinterpret_cast<float2*>(Pb + b1 + col) = o1;
            float2 o2; o2.x = acc[mt][nt][2]; o2.y = acc[mt][nt][3];
            *reinterpret_cast<float2*>(Pb + b2 + col) = o2;
        }
    }
}

// ---------------- kernel 5: fold split-K partials into X1_t --------------
__global__ __launch_bounds__(256) void k_fix(float* __restrict__ x1o) {
    const size_t i = ((size_t)blockIdx.x * 256 + threadIdx.x) << 2;
    const float inv = 1.0f / 1024.0f;
    float4 p0 = *reinterpret_cast<const float4*>(g_part0 + i);
    float4 p1 = *reinterpret_cast<const float4*>(g_part1 + i);
    float4 x  = *reinterpret_cast<const float4*>(x1o + i);
    x.x += (p0.x + p1.x) * inv;
    x.y += (p0.y + p1.y) * inv;
    x.z += (p0.z + p1.z) * inv;
    x.w += (p0.w + p1.w) * inv;
    *reinterpret_cast<float4*>(x1o + i) = x;
}

// ---------------- launch ----------------
extern "C" void kernel_launch(void* const* d_in, const int* in_sizes, int n_in,
                              void* d_out, int out_size)
{
    const float* A      = (const float*)d_in[0];
    const float* X      = (const float*)d_in[1];
    const float* coeffs = (const float*)d_in[2];
    const float* wA1    = (const float*)d_in[3];
    const float* wA2    = (const float*)d_in[4];
    const float* w11    = (const float*)d_in[5];
    const float* w12    = (const float*)d_in[6];
    const float* w13    = (const float*)d_in[7];
    const float* w14    = (const float*)d_in[8];
    const float* w15    = (const float*)d_in[9];
    const float* w16    = (const float*)d_in[10];
    const float* w21    = (const float*)d_in[11];
    const float* w22    = (const float*)d_in[12];
    const float* w23    = (const float*)d_in[13];
    const float* w24    = (const float*)d_in[14];
    const float* w25    = (const float*)d_in[15];
    const float* w26    = (const float*)d_in[16];

    float* out = (float*)d_out;
    float* x1o = out + OUT_OFF;

    const int NODE_SMEM = (128*DD + 2*64*68) * (int)sizeof(float);  // 67584
    cudaFuncSetAttribute(k_node, cudaFuncAttributeMaxDynamicSharedMemorySize, NODE_SMEM);
    const int GEMM_SMEM = 2 * STG_U * (int)sizeof(uint32_t);        // 61440
    cudaFuncSetAttribute(k_gemm, cudaFuncAttributeMaxDynamicSharedMemorySize, GEMM_SMEM);

    k_row_stats  <<<2048, 256>>>(A, X, coeffs, wA1);
    k_batch_stats<<<16,   256>>>(X, coeffs, wA2, w12, w15, w16, w22, w25, w26);
    k_node       <<<dim3(8,16), 256, NODE_SMEM>>>(X, w11, w13, w14, w21, w23, w24, x1o);
    k_gemm       <<<dim3(8,16,2), 256, GEMM_SMEM>>>(A, coeffs, out);
    k_fix        <<<(NB*NN*DD)/(256*4), 256>>>(x1o);
}